// round 12
// baseline (speedup 1.0000x reference)
#include <cuda_runtime.h>
#include <cuda_fp16.h>
#include <math.h>
#include <stdint.h>

// Problem constants
#define BB   4
#define SS   4096
#define DD   1024
#define HH   8
#define DK_  128
#define SEG_ 512
#define NSEG 8
#define DH_  4096
#define MROWS (BB*SS)   // 16384
#define QS   3072       // fused qkv row stride
#define NCH  4          // segkv position chunks per segment

// ---------------- scratch ----------------
__device__ __half g_qkvh[(size_t)MROWS*QS];            // fp16 q|k|v
__device__ float g_x1[(size_t)MROWS*DD];
__device__ float g_ff[(size_t)MROWS*DH_];              // reused: FFN1 hi fp16 output
__device__ float g_msp[(size_t)NSEG*NCH*BB*HH*DK_*DK_]; // partial seg outer products
__device__ float g_mp [(size_t)NSEG*BB*HH*DK_*DK_];
__device__ float g_zsp[(size_t)NSEG*NCH*BB*HH*DK_];
__device__ float g_zp [(size_t)NSEG*BB*HH*DK_];
// fp16 activation buffer [M][1024] (hi only)
__device__ __half g_ah[(size_t)MROWS*DD];
// transposed fp16 weights [N][K]
__device__ __half g_bqkv[(size_t)QS*DD];
__device__ __half g_bo[(size_t)DD*DD];
__device__ __half g_bw1[(size_t)DH_*DD];
__device__ __half g_bw2[(size_t)DD*DH_];

__device__ __forceinline__ float gelu_f(float x) {
    float x3 = x*x*x;
    float t = tanhf(0.7978845608028654f*(x + 0.044715f*x3));
    return 0.5f*x*(1.f + t);
}

// ================= PTX helpers =================
__device__ __forceinline__ uint32_t smem_u32(const void* p) {
    uint32_t a;
    asm("{ .reg .u64 t; cvta.to.shared.u64 t, %1; cvt.u32.u64 %0, t; }" : "=r"(a) : "l"(p));
    return a;
}
__device__ __forceinline__ void cpa16(uint32_t d, const void* s) {
    asm volatile("cp.async.cg.shared.global [%0], [%1], 16;"
                 :: "r"(d), "l"(__cvta_generic_to_global((void*)s)) : "memory");
}
#define SWZ(x) ((x) ^ (((x) >> 3) & 0x70))

#define LDSM4(r0,r1,r2,r3,addr) \
    asm volatile("ldmatrix.sync.aligned.m8n8.x4.shared.b16 {%0,%1,%2,%3}, [%4];" \
                 : "=r"(r0),"=r"(r1),"=r"(r2),"=r"(r3) : "r"(addr))

#define MMA16816(d, a, b) \
    asm volatile("mma.sync.aligned.m16n8k16.row.col.f32.f16.f16.f32 " \
                 "{%0,%1,%2,%3}, {%4,%5,%6,%7}, {%8,%9}, {%0,%1,%2,%3};" \
                 : "+f"((d)[0]),"+f"((d)[1]),"+f"((d)[2]),"+f"((d)[3]) \
                 : "r"((a)[0]),"r"((a)[1]),"r"((a)[2]),"r"((a)[3]), \
                   "r"((b)[0]),"r"((b)[1]))

// 8 halves (uint4) -> two float4
__device__ __forceinline__ void h8_to_f8(uint4 u, float4& lo, float4& hi) {
    __half2* h = (__half2*)&u;
    float2 f0 = __half22float2(h[0]);
    float2 f1 = __half22float2(h[1]);
    float2 f2 = __half22float2(h[2]);
    float2 f3 = __half22float2(h[3]);
    lo = make_float4(f0.x, f0.y, f1.x, f1.y);
    hi = make_float4(f2.x, f2.y, f3.x, f3.y);
}

// ---------------- LayerNorm -> fp16 (hi only) ----------------
__global__ void ln_kernel(const float* __restrict__ x, const float* __restrict__ gamma,
                          const float* __restrict__ beta, __half* __restrict__ Ah) {
    __shared__ float s1[256], s2[256];
    const int row = blockIdx.x;
    const int tid = threadIdx.x;
    const float* xr = x + (size_t)row*DD;
    float4 v = *(const float4*)&xr[tid*4];
    float s  = v.x+v.y+v.z+v.w;
    float ss = v.x*v.x+v.y*v.y+v.z*v.z+v.w*v.w;
    s1[tid]=s; s2[tid]=ss; __syncthreads();
    for (int o=128;o>0;o>>=1){ if(tid<o){s1[tid]+=s1[tid+o]; s2[tid]+=s2[tid+o];} __syncthreads(); }
    float mu  = s1[0]*(1.f/DD);
    float var = s2[0]*(1.f/DD) - mu*mu;
    float inv = rsqrtf(var + 1e-5f);
    float4 g  = *(const float4*)&gamma[tid*4];
    float4 bt = *(const float4*)&beta[tid*4];
    float o0 = (v.x-mu)*inv*g.x + bt.x;
    float o1 = (v.y-mu)*inv*g.y + bt.y;
    float o2 = (v.z-mu)*inv*g.z + bt.z;
    float o3 = (v.w-mu)*inv*g.w + bt.w;
    size_t base = (size_t)row*DD + tid*4;
    *(__half2*)&Ah[base]   = __halves2half2(__float2half_rn(o0), __float2half_rn(o1));
    *(__half2*)&Ah[base+2] = __halves2half2(__float2half_rn(o2), __float2half_rn(o3));
}

// ---------------- Weight prep: W[K,N] -> Bp[N][K] fp16 (transposed) ----------------
__global__ void prep_w_kernel(const float* __restrict__ W, __half* __restrict__ Bp,
                              int K, int N) {
    __shared__ float ts[32][33];
    const int n0 = blockIdx.x*32, k0 = blockIdx.y*32;
    const int tx = threadIdx.x, ty = threadIdx.y;   // (32,8)
    #pragma unroll
    for (int i = 0; i < 4; i++)
        ts[ty+8*i][tx] = W[(size_t)(k0+ty+8*i)*N + n0+tx];
    __syncthreads();
    #pragma unroll
    for (int i = 0; i < 4; i++) {
        int nl = ty + 8*i;
        Bp[(size_t)(n0+nl)*K + k0+tx] = __float2half_rn(ts[tx][nl]);
    }
}

// ---------------- mma.sync fp16 GEMM (hi-only inputs) ----------------
// splitOut: 0 = fp32 C, 2 = fp16 hi only. ldc: row stride for outputs/add.
#define GBK 64
#define NSTG 3
#define STB 16384
#define STAGE_BYTES (2*STB)
#define HG_SMEM (NSTG*STAGE_BYTES)

__global__ __launch_bounds__(256, 2) void hgemm_kernel(
    const __half* __restrict__ Ah, const __half* __restrict__ Bp,
    const float* __restrict__ bias, const float* __restrict__ add,
    float* __restrict__ C, __half* __restrict__ Cah,
    int M, int N, int ldc, int K, int act, int splitOut)
{
    extern __shared__ char dsm[];
    const uint32_t sb = smem_u32(dsm);
    const int tid = threadIdx.x;
    const int lane = tid & 31, wid = tid >> 5;
    const int row0 = blockIdx.y * 128, col0 = blockIdx.x * 128;
    const int NT = K / GBK;

    const int wm = (wid >> 2) * 64;
    const int wn = (wid & 3) * 32;

    float acc[4][4][4];
    #pragma unroll
    for (int i=0;i<4;i++)
        #pragma unroll
        for (int j=0;j<4;j++)
            #pragma unroll
            for (int c=0;c<4;c++) acc[i][j][c]=0.f;

    auto load_tile = [&](int t, int s) {
        int k0 = t * GBK;
        uint32_t stA = sb + s*STAGE_BYTES;
        uint32_t stB = stA + STB;
        #pragma unroll
        for (int i = 0; i < 4; i++) {
            int ch = i*256 + tid;
            int r = ch >> 3, c = (ch & 7) * 8;
            cpa16(stA + SWZ(ch*16), Ah + (size_t)(row0 + r)*K + k0 + c);
            cpa16(stB + SWZ(ch*16), Bp + (size_t)(col0 + r)*K + k0 + c);
        }
        asm volatile("cp.async.commit_group;" ::: "memory");
    };

    load_tile(0, 0);
    if (NT > 1) load_tile(1, 1);

    const int aRow = wm + (lane & 15);
    const int aColB = ((lane >> 4) & 1) * 16;
    const int bRow = wn + (lane & 7) + ((lane >> 4) & 1) * 8;
    const int bColB = ((lane >> 3) & 1) * 16;

    for (int t = 0; t < NT; t++) {
        if (t < NT-1) asm volatile("cp.async.wait_group 1;" ::: "memory");
        else          asm volatile("cp.async.wait_group 0;" ::: "memory");
        __syncthreads();
        if (t + 2 < NT) load_tile(t + 2, (t + 2) % NSTG);
        uint32_t stA = sb + (t % NSTG)*STAGE_BYTES;
        uint32_t stB = stA + STB;
        #pragma unroll
        for (int kk = 0; kk < 4; kk++) {
            uint32_t af[4][4];
            #pragma unroll
            for (int mt = 0; mt < 4; mt++) {
                uint32_t addr = stA + SWZ((uint32_t)(aRow + mt*16)*128 + kk*32 + aColB);
                LDSM4(af[mt][0], af[mt][1], af[mt][2], af[mt][3], addr);
            }
            uint32_t bf[4][2];
            #pragma unroll
            for (int nt2 = 0; nt2 < 2; nt2++) {
                uint32_t r0,r1,r2,r3;
                uint32_t addr = stB + SWZ((uint32_t)(bRow + nt2*16)*128 + kk*32 + bColB);
                LDSM4(r0, r1, r2, r3, addr);
                bf[nt2*2][0]=r0; bf[nt2*2][1]=r1; bf[nt2*2+1][0]=r2; bf[nt2*2+1][1]=r3;
            }
            #pragma unroll
            for (int mt = 0; mt < 4; mt++)
                #pragma unroll
                for (int nt = 0; nt < 4; nt++)
                    MMA16816(acc[mt][nt], af[mt], bf[nt]);
        }
        __syncthreads();
    }

    const int erow = lane >> 2, ecol = (lane & 3) * 2;
    #pragma unroll
    for (int mt = 0; mt < 4; mt++) {
        #pragma unroll
        for (int half_ = 0; half_ < 2; half_++) {
            int row = row0 + wm + mt*16 + erow + half_*8;
            size_t rbase = (size_t)row * ldc;
            #pragma unroll
            for (int nt = 0; nt < 4; nt++) {
                int col = col0 + wn + nt*8 + ecol;
                float v0 = acc[mt][nt][half_*2+0];
                float v1 = acc[mt][nt][half_*2+1];
                if (bias) { v0 += bias[col]; v1 += bias[col+1]; }
                if (act)  { v0 = gelu_f(v0); v1 = gelu_f(v1); }
                if (add)  {
                    const float2 a2 = *(const float2*)&add[rbase + col];
                    v0 += a2.x; v1 += a2.y;
                }
                if (splitOut) {
                    *(__half2*)&Cah[rbase + col] =
                        __halves2half2(__float2half_rn(v0), __float2half_rn(v1));
                } else {
                    *(float2*)&C[rbase + col] = make_float2(v0, v1);
                }
            }
        }
    }
}

// ---------------- Per-segment partial memory contributions ----------------
// grid (NSEG, BB*HH, NCH). Each block: 128 positions -> partial S, z.
__global__ void segkv_kernel(const __half* __restrict__ k, const __half* __restrict__ v,
                             float* __restrict__ msp, float* __restrict__ zsp)
{
    __shared__ float sks[32][128];
    __shared__ float svs[32][128];
    __shared__ float zacc[128];
    const int seg = blockIdx.x, bh = blockIdx.y, ch = blockIdx.z;
    const int b = bh >> 3, h = bh & 7;
    const int tid = threadIdx.x;
    const int ty = tid >> 4, tx = tid & 15;
    float acc[8][8];
    #pragma unroll
    for (int i=0;i<8;i++)
        #pragma unroll
        for (int j=0;j<8;j++) acc[i][j]=0.f;
    if (tid < 128) zacc[tid] = 0.f;
    size_t base = ((size_t)b*SS + seg*SEG_ + ch*128)*QS + h*DK_;
    for (int p0 = 0; p0 < 128; p0 += 32) {
        __syncthreads();
        for (int i = tid; i < 512; i += 256) {   // 32 rows x 16 chunks of 8 halves
            int row = i >> 4, c8 = (i & 15)*8;
            uint4 ku = *(const uint4*)&k[base + (size_t)(p0+row)*QS + c8];
            float4 klo, khi;
            h8_to_f8(ku, klo, khi);
            klo.x = klo.x>0.f?klo.x+1.f:__expf(klo.x);
            klo.y = klo.y>0.f?klo.y+1.f:__expf(klo.y);
            klo.z = klo.z>0.f?klo.z+1.f:__expf(klo.z);
            klo.w = klo.w>0.f?klo.w+1.f:__expf(klo.w);
            khi.x = khi.x>0.f?khi.x+1.f:__expf(khi.x);
            khi.y = khi.y>0.f?khi.y+1.f:__expf(khi.y);
            khi.z = khi.z>0.f?khi.z+1.f:__expf(khi.z);
            khi.w = khi.w>0.f?khi.w+1.f:__expf(khi.w);
            *(float4*)&sks[row][c8]   = klo;
            *(float4*)&sks[row][c8+4] = khi;
            uint4 vu = *(const uint4*)&v[base + (size_t)(p0+row)*QS + c8];
            float4 vlo, vhi;
            h8_to_f8(vu, vlo, vhi);
            *(float4*)&svs[row][c8]   = vlo;
            *(float4*)&svs[row][c8+4] = vhi;
        }
        __syncthreads();
        if (tid < 128) {
            float za = 0.f;
            for (int p = 0; p < 32; p++) za += sks[p][tid];
            zacc[tid] += za;
        }
        #pragma unroll 4
        for (int p = 0; p < 32; p++) {
            float4 k0 = *(const float4*)&sks[p][ty*8];
            float4 k1 = *(const float4*)&sks[p][ty*8+4];
            float4 v0 = *(const float4*)&svs[p][tx*8];
            float4 v1 = *(const float4*)&svs[p][tx*8+4];
            float kr[8] = {k0.x,k0.y,k0.z,k0.w,k1.x,k1.y,k1.z,k1.w};
            float vr[8] = {v0.x,v0.y,v0.z,v0.w,v1.x,v1.y,v1.z,v1.w};
            #pragma unroll
            for (int i=0;i<8;i++)
                #pragma unroll
                for (int j=0;j<8;j++) acc[i][j] += kr[i]*vr[j];
        }
    }
    const int slice = seg*NCH + ch;
    size_t obase = ((size_t)slice*32 + bh)*DK_*DK_;
    #pragma unroll
    for (int i=0;i<8;i++)
        #pragma unroll
        for (int j=0;j<8;j++)
            msp[obase + (size_t)(ty*8+i)*DK_ + tx*8+j] = acc[i][j];
    if (tid < 128) zsp[((size_t)slice*32 + bh)*DK_ + tid] = zacc[tid];
}

// ---------------- Exclusive prefix over 8 segments (sum NCH partials) ----------------
__global__ void prefix_kernel(const float* __restrict__ msp, const float* __restrict__ zsp,
                              float* __restrict__ mp, float* __restrict__ zp)
{
    size_t idx = (size_t)blockIdx.x*256 + threadIdx.x;
    const size_t stride = (size_t)BB*HH*DK_*DK_;
    if (idx < stride) {
        float a = 0.f;
        #pragma unroll
        for (int t = 0; t < NSEG; t++) {
            mp[t*stride + idx] = a;
            #pragma unroll
            for (int c = 0; c < NCH; c++)
                a += msp[(size_t)(t*NCH + c)*stride + idx];
        }
    }
    if (idx < (size_t)BB*HH*DK_) {
        const size_t zstr = (size_t)BB*HH*DK_;
        float a = 1.f/128.f;
        #pragma unroll
        for (int t = 0; t < NSEG; t++) {
            zp[t*zstr + idx] = a;
            #pragma unroll
            for (int c = 0; c < NCH; c++)
                a += zsp[(size_t)(t*NCH + c)*zstr + idx];
        }
    }
}

// ---------------- Attention: register-blocked + shuffle softmax (fp16 qkv in) ----------------
#define AP 132
#define SPP 68
#define ATTN_SMEM_FLOATS (64*AP*2 + 64*128 + 64*SPP + 128 + 3*64)
__global__ __launch_bounds__(256, 1) void attn_kernel(
    const __half* __restrict__ q, const __half* __restrict__ k,
    const __half* __restrict__ v, const float* __restrict__ memp,
    const float* __restrict__ zp, const float* __restrict__ betas,
    __half* __restrict__ Oah)
{
    extern __shared__ float sh[];
    float* Qs  = sh;                 // [64][AP]
    float* Ks  = Qs + 64*AP;         // [64][AP]  (later reused for sq)
    float* Vs  = Ks + 64*AP;         // [64][128] (later reused for M chunks)
    float* Spt = Vs + 64*128;        // [64 c][SPP]
    float* Zs  = Spt + 64*SPP;       // [128]
    float* mrow = Zs + 128;
    float* lrow = mrow + 64;
    float* drow = lrow + 64;

    const int qt = blockIdx.x, seg = blockIdx.y;
    const int b = blockIdx.z >> 3, h = blockIdx.z & 7;
    const int tid = threadIdx.x;
    const int ty = tid >> 4, tx = tid & 15;

    const float* Z = zp + (((size_t)seg*BB + b)*HH + h)*DK_;
    size_t qbase = ((size_t)b*SS + seg*SEG_ + qt*64)*QS + h*DK_;
    #pragma unroll
    for (int i = tid; i < 64*16; i += 256) {
        int row = i >> 4, c8 = (i & 15)*8;
        uint4 u = *(const uint4*)&q[qbase + (size_t)row*QS + c8];
        float4 lo, hi;
        h8_to_f8(u, lo, hi);
        *(float4*)&Qs[row*AP + c8]   = lo;
        *(float4*)&Qs[row*AP + c8+4] = hi;
    }
    if (tid < 128) Zs[tid] = Z[tid];
    if (tid < 64) { mrow[tid] = -INFINITY; lrow[tid] = 0.f; }
    float o[4][8];
    #pragma unroll
    for (int i=0;i<4;i++)
        #pragma unroll
        for (int j=0;j<8;j++) o[i][j]=0.f;
    __syncthreads();

    const float scale = 0.08838834764831845f;
    for (int kt = 0; kt <= qt; kt++) {
        size_t kbase = ((size_t)b*SS + seg*SEG_ + kt*64)*QS + h*DK_;
        #pragma unroll
        for (int i = tid; i < 64*16; i += 256) {
            int row = i >> 4, c8 = (i & 15)*8;
            uint4 ku = *(const uint4*)&k[kbase + (size_t)row*QS + c8];
            float4 lo, hi;
            h8_to_f8(ku, lo, hi);
            *(float4*)&Ks[row*AP + c8]   = lo;
            *(float4*)&Ks[row*AP + c8+4] = hi;
            uint4 vu = *(const uint4*)&v[kbase + (size_t)row*QS + c8];
            h8_to_f8(vu, lo, hi);
            *(float4*)&Vs[row*128 + c8]   = lo;
            *(float4*)&Vs[row*128 + c8+4] = hi;
        }
        __syncthreads();

        // S = Q @ K^T (4x4 per thread)
        float s[4][4];
        #pragma unroll
        for (int i=0;i<4;i++)
            #pragma unroll
            for (int j=0;j<4;j++) s[i][j]=0.f;
        #pragma unroll 4
        for (int d = 0; d < 128; d += 4) {
            float4 qv[4], kv[4];
            #pragma unroll
            for (int i=0;i<4;i++) qv[i] = *(const float4*)&Qs[(ty*4+i)*AP + d];
            #pragma unroll
            for (int j=0;j<4;j++) kv[j] = *(const float4*)&Ks[(tx*4+j)*AP + d];
            #pragma unroll
            for (int i=0;i<4;i++)
                #pragma unroll
                for (int j=0;j<4;j++)
                    s[i][j] += qv[i].x*kv[j].x + qv[i].y*kv[j].y
                             + qv[i].z*kv[j].z + qv[i].w*kv[j].w;
        }
        // scale + causal mask in registers
        #pragma unroll
        for (int i=0;i<4;i++)
            #pragma unroll
            for (int j=0;j<4;j++) {
                float vv = s[i][j]*scale;
                if (kt == qt && (tx*4+j) > (ty*4+i)) vv = -INFINITY;
                s[i][j] = vv;
            }

        // register+shuffle softmax stats (16-lane butterfly across tx)
        float al_[4], ls_[4], mx_[4];
        #pragma unroll
        for (int i=0;i<4;i++) {
            float rm = fmaxf(fmaxf(s[i][0],s[i][1]), fmaxf(s[i][2],s[i][3]));
            #pragma unroll
            for (int off = 1; off < 16; off <<= 1)
                rm = fmaxf(rm, __shfl_xor_sync(0xffffffffu, rm, off));
            float mold = mrow[ty*4+i];
            float mx = fmaxf(mold, rm);
            mx_[i] = mx;
            al_[i] = __expf(mold - mx);
            float ps = 0.f;
            #pragma unroll
            for (int j=0;j<4;j++) {
                float p = __expf(s[i][j] - mx);
                Spt[(tx*4+j)*SPP + ty*4+i] = p;
                ps += p;
            }
            #pragma unroll
            for (int off = 1; off < 16; off <<= 1)
                ps += __shfl_xor_sync(0xffffffffu, ps, off);
            ls_[i] = ps;
        }
        __syncthreads();
        if (tx == 0) {
            #pragma unroll
            for (int i=0;i<4;i++) {
                int r = ty*4 + i;
                mrow[r] = mx_[i];
                lrow[r] = lrow[r]*al_[i] + ls_[i];
            }
        }

        // rescale + PV
        #pragma unroll
        for (int i=0;i<4;i++)
            #pragma unroll
            for (int j=0;j<8;j++) o[i][j] *= al_[i];
        #pragma unroll 2
        for (int c = 0; c < 64; c++) {
            float4 p4 = *(const float4*)&Spt[c*SPP + ty*4];
            float pp[4] = {p4.x, p4.y, p4.z, p4.w};
            float4 v0 = *(const float4*)&Vs[c*128 + tx*8];
            float4 v1 = *(const float4*)&Vs[c*128 + tx*8 + 4];
            float vr[8] = {v0.x,v0.y,v0.z,v0.w,v1.x,v1.y,v1.z,v1.w};
            #pragma unroll
            for (int i=0;i<4;i++)
                #pragma unroll
                for (int j=0;j<8;j++) o[i][j] += pp[i]*vr[j];
        }
        __syncthreads();
    }

    // ---- retrieval: sq = elu(q)+1 into Ks ----
    #pragma unroll
    for (int i = tid; i < 64*128; i += 256) {
        int row = i >> 7, d = i & 127;
        float qv = Qs[row*AP + d];
        Ks[row*AP + d] = qv > 0.f ? qv + 1.f : __expf(qv);
    }
    __syncthreads();
    if (tid < 64) {
        float ds = 0.f;
        #pragma unroll 4
        for (int d = 0; d < 128; d += 4) {
            float4 sq4 = *(const float4*)&Ks[tid*AP + d];
            float4 z4  = *(const float4*)&Zs[d];
            ds += sq4.x*z4.x + sq4.y*z4.y + sq4.z*z4.z + sq4.w*z4.w;
        }
        drow[tid] = ds;
    }

    const float* M = memp + (((size_t)seg*BB + b)*HH + h)*DK_*DK_;
    float am[4][8];
    #pragma unroll
    for (int i=0;i<4;i++)
        #pragma unroll
        for (int j=0;j<8;j++) am[i][j]=0.f;
    for (int d0 = 0; d0 < 128; d0 += 32) {
        __syncthreads();
        #pragma unroll
        for (int i = tid; i < 32*32; i += 256) {
            int row = i >> 5, c4 = (i & 31)*4;
            *(float4*)&Vs[row*128 + c4] = *(const float4*)&M[(size_t)(d0+row)*128 + c4];
        }
        __syncthreads();
        #pragma unroll 2
        for (int dd = 0; dd < 32; dd += 4) {
            float sqa[4][4];
            #pragma unroll
            for (int i=0;i<4;i++) {
                float4 s4 = *(const float4*)&Ks[(ty*4+i)*AP + d0 + dd];
                sqa[i][0]=s4.x; sqa[i][1]=s4.y; sqa[i][2]=s4.z; sqa[i][3]=s4.w;
            }
            #pragma unroll
            for (int t = 0; t < 4; t++) {
                float4 m0 = *(const float4*)&Vs[(dd+t)*128 + tx*8];
                float4 m1 = *(const float4*)&Vs[(dd+t)*128 + tx*8 + 4];
                float mr[8] = {m0.x,m0.y,m0.z,m0.w,m1.x,m1.y,m1.z,m1.w};
                #pragma unroll
                for (int i=0;i<4;i++)
                    #pragma unroll
                    for (int j=0;j<8;j++) am[i][j] += sqa[i][t]*mr[j];
            }
        }
    }

    // ---- gate + write hi-only fp16 output (row stride DD) ----
    float gte[8];
    #pragma unroll
    for (int j=0;j<8;j++)
        gte[j] = 1.f / (1.f + __expf(-betas[h*DK_ + tx*8 + j]));
    #pragma unroll
    for (int i=0;i<4;i++) {
        int r = ty*4 + i;
        float dinv = 1.f / drow[r];
        float linv = 1.f / lrow[r];
        size_t ob = ((size_t)b*SS + seg*SEG_ + qt*64 + r)*DD + h*DK_ + tx*8;
        #pragma unroll
        for (int j=0;j<8;j+=2) {
            float u0 = gte[j]  *(am[i][j]  *dinv) + (1.f-gte[j])  *(o[i][j]  *linv);
            float u1 = gte[j+1]*(am[i][j+1]*dinv) + (1.f-gte[j+1])*(o[i][j+1]*linv);
            *(__half2*)&Oah[ob + j] = __halves2half2(__float2half_rn(u0), __float2half_rn(u1));
        }
    }
}

// ---------------- launch ----------------
extern "C" void kernel_launch(void* const* d_in, const int* in_sizes, int n_in,
                              void* d_out, int out_size)
{
    const float* x     = (const float*)d_in[0];
    const float* ln_g  = (const float*)d_in[1];
    const float* ln_b  = (const float*)d_in[2];
    const float* Wq    = (const float*)d_in[3];
    const float* Wk    = (const float*)d_in[4];
    const float* Wv    = (const float*)d_in[5];
    const float* Wo    = (const float*)d_in[6];
    const float* betas = (const float*)d_in[7];
    const float* w1    = (const float*)d_in[8];
    const float* b1    = (const float*)d_in[9];
    const float* w2    = (const float*)d_in[10];
    const float* b2    = (const float*)d_in[11];
    float* out = (float*)d_out;

    float *x1, *ff, *msp, *mp, *zsp, *zp;
    __half *qkvh, *ah, *bqkv, *bo, *bw1, *bw2;
    cudaGetSymbolAddress((void**)&qkvh, g_qkvh);
    cudaGetSymbolAddress((void**)&x1, g_x1);
    cudaGetSymbolAddress((void**)&ff, g_ff);
    cudaGetSymbolAddress((void**)&msp, g_msp);
    cudaGetSymbolAddress((void**)&mp, g_mp);
    cudaGetSymbolAddress((void**)&zsp, g_zsp);
    cudaGetSymbolAddress((void**)&zp, g_zp);
    cudaGetSymbolAddress((void**)&ah, g_ah);
    cudaGetSymbolAddress((void**)&bqkv, g_bqkv);
    cudaGetSymbolAddress((void**)&bo, g_bo);
    cudaGetSymbolAddress((void**)&bw1, g_bw1);
    cudaGetSymbolAddress((void**)&bw2, g_bw2);

    __half* ah2 = (__half*)ff;     // FFN1 hi-only output

    const int attn_smem = ATTN_SMEM_FLOATS * 4;
    cudaFuncSetAttribute(attn_kernel, cudaFuncAttributeMaxDynamicSharedMemorySize, attn_smem);
    cudaFuncSetAttribute(hgemm_kernel, cudaFuncAttributeMaxDynamicSharedMemorySize, HG_SMEM);

    dim3 wblk(32, 8);

    // weight prep: fused QKV rows [0:1024)=Wq, [1024:2048)=Wk, [2048:3072)=Wv
    prep_w_kernel<<<dim3(1024/32, 1024/32), wblk>>>(Wq, bqkv,                      1024, 1024);
    prep_w_kernel<<<dim3(1024/32, 1024/32), wblk>>>(Wk, bqkv + (size_t)1024*1024,  1024, 1024);
    prep_w_kernel<<<dim3(1024/32, 1024/32), wblk>>>(Wv, bqkv + (size_t)2048*1024,  1024, 1024);
    prep_w_kernel<<<dim3(1024/32, 1024/32), wblk>>>(Wo, bo, 1024, 1024);
    prep_w_kernel<<<dim3(4096/32, 1024/32), wblk>>>(w1, bw1, 1024, 4096);
    prep_w_kernel<<<dim3(1024/32, 4096/32), wblk>>>(w2, bw2, 4096, 1024);

    // 1) LN1 -> fp16 hi
    ln_kernel<<<MROWS, 256>>>(x, ln_g, ln_b, ah);
    // 2) fused QKV projection (N=3072) -> fp16 qkv
    hgemm_kernel<<<dim3(QS/128, MROWS/128), 256, HG_SMEM>>>(ah, bqkv, nullptr, nullptr,
                                                            nullptr, qkvh, MROWS, QS, QS, DD, 0, 2);
    // 3-5) infini-attention
    segkv_kernel<<<dim3(NSEG, BB*HH, NCH), 256>>>(qkvh + 1024, qkvh + 2048, msp, zsp);
    prefix_kernel<<<(BB*HH*DK_*DK_)/256, 256>>>(msp, zsp, mp, zp);
    attn_kernel<<<dim3(8, NSEG, BB*HH), 256, attn_smem>>>(qkvh, qkvh + 1024, qkvh + 2048,
                                                          mp, zp, betas, ah);
    // 6) output projection + residual
    dim3 g1(DD/128, MROWS/128);
    hgemm_kernel<<<g1, 256, HG_SMEM>>>(ah, bo, nullptr, x, x1, nullptr,
                                       MROWS, DD, DD, DD, 0, 0);
    // 7) LN2 -> fp16 hi
    ln_kernel<<<MROWS, 256>>>(x1, ln_g, ln_b, ah);
    // 8) FFN1 + bias + gelu -> fp16 hi
    hgemm_kernel<<<dim3(DH_/128, MROWS/128), 256, HG_SMEM>>>(ah, bw1, b1, nullptr, nullptr,
                                                             ah2, MROWS, DH_, DH_, DD, 1, 2);
    // 9) FFN2 + bias + residual -> out
    hgemm_kernel<<<dim3(DD/128, MROWS/128), 256, HG_SMEM>>>(ah2, bw2, b2, x1, out,
                                                            nullptr, MROWS, DD, DD, DH_, 0, 0);
}

// round 13
// speedup vs baseline: 1.6043x; 1.6043x over previous
#include <cuda_runtime.h>
#include <cuda_fp16.h>
#include <math.h>
#include <stdint.h>

// Problem constants
#define BB   4
#define SS   4096
#define DD   1024
#define HH   8
#define DK_  128
#define SEG_ 512
#define NSEG 8
#define DH_  4096
#define MROWS (BB*SS)   // 16384
#define QS   3072       // fused qkv row stride
#define NCH  4          // segkv position chunks per segment

// ---------------- scratch ----------------
__device__ __half g_qkvh[(size_t)MROWS*QS];            // fp16 q|k|v
__device__ float g_x1[(size_t)MROWS*DD];
__device__ float g_ff[(size_t)MROWS*DH_];              // reused: FFN1 hi fp16 output
__device__ float g_msp[(size_t)NSEG*NCH*BB*HH*DK_*DK_]; // partial seg outer products
__device__ __half g_mph[(size_t)NSEG*BB*HH*DK_*DK_];    // fp16 prefix memory
__device__ float g_zsp[(size_t)NSEG*NCH*BB*HH*DK_];
__device__ float g_zp [(size_t)NSEG*BB*HH*DK_];
// fp16 activation buffer [M][1024] (hi only)
__device__ __half g_ah[(size_t)MROWS*DD];
// transposed fp16 weights [N][K]
__device__ __half g_bqkv[(size_t)QS*DD];
__device__ __half g_bo[(size_t)DD*DD];
__device__ __half g_bw1[(size_t)DH_*DD];
__device__ __half g_bw2[(size_t)DD*DH_];

__device__ __forceinline__ float gelu_f(float x) {
    float x3 = x*x*x;
    float t = tanhf(0.7978845608028654f*(x + 0.044715f*x3));
    return 0.5f*x*(1.f + t);
}

// ================= PTX helpers =================
__device__ __forceinline__ uint32_t smem_u32(const void* p) {
    uint32_t a;
    asm("{ .reg .u64 t; cvta.to.shared.u64 t, %1; cvt.u32.u64 %0, t; }" : "=r"(a) : "l"(p));
    return a;
}
__device__ __forceinline__ void cpa16(uint32_t d, const void* s) {
    asm volatile("cp.async.cg.shared.global [%0], [%1], 16;"
                 :: "r"(d), "l"(__cvta_generic_to_global((void*)s)) : "memory");
}
#define SWZ(x) ((x) ^ (((x) >> 3) & 0x70))

#define LDSM4(r0,r1,r2,r3,addr) \
    asm volatile("ldmatrix.sync.aligned.m8n8.x4.shared.b16 {%0,%1,%2,%3}, [%4];" \
                 : "=r"(r0),"=r"(r1),"=r"(r2),"=r"(r3) : "r"(addr))

#define LDSM4T(r0,r1,r2,r3,addr) \
    asm volatile("ldmatrix.sync.aligned.m8n8.x4.trans.shared.b16 {%0,%1,%2,%3}, [%4];" \
                 : "=r"(r0),"=r"(r1),"=r"(r2),"=r"(r3) : "r"(addr))

#define MMA16816(d, a, b) \
    asm volatile("mma.sync.aligned.m16n8k16.row.col.f32.f16.f16.f32 " \
                 "{%0,%1,%2,%3}, {%4,%5,%6,%7}, {%8,%9}, {%0,%1,%2,%3};" \
                 : "+f"((d)[0]),"+f"((d)[1]),"+f"((d)[2]),"+f"((d)[3]) \
                 : "r"((a)[0]),"r"((a)[1]),"r"((a)[2]),"r"((a)[3]), \
                   "r"((b)[0]),"r"((b)[1]))

// swizzled byte offsets: 256B-pitch rows (128 fp16) and 128B-pitch rows (64 fp16)
__device__ __forceinline__ uint32_t swz256(int row, int e) {
    return SWZ((uint32_t)((row*2 + (e>>6))*128 + (e&63)*2));
}
__device__ __forceinline__ uint32_t swz128(int row, int e) {
    return SWZ((uint32_t)(row*128 + e*2));
}

// ---------------- LayerNorm -> fp16 (hi only) ----------------
__global__ void ln_kernel(const float* __restrict__ x, const float* __restrict__ gamma,
                          const float* __restrict__ beta, __half* __restrict__ Ah) {
    __shared__ float s1[256], s2[256];
    const int row = blockIdx.x;
    const int tid = threadIdx.x;
    const float* xr = x + (size_t)row*DD;
    float4 v = *(const float4*)&xr[tid*4];
    float s  = v.x+v.y+v.z+v.w;
    float ss = v.x*v.x+v.y*v.y+v.z*v.z+v.w*v.w;
    s1[tid]=s; s2[tid]=ss; __syncthreads();
    for (int o=128;o>0;o>>=1){ if(tid<o){s1[tid]+=s1[tid+o]; s2[tid]+=s2[tid+o];} __syncthreads(); }
    float mu  = s1[0]*(1.f/DD);
    float var = s2[0]*(1.f/DD) - mu*mu;
    float inv = rsqrtf(var + 1e-5f);
    float4 g  = *(const float4*)&gamma[tid*4];
    float4 bt = *(const float4*)&beta[tid*4];
    float o0 = (v.x-mu)*inv*g.x + bt.x;
    float o1 = (v.y-mu)*inv*g.y + bt.y;
    float o2 = (v.z-mu)*inv*g.z + bt.z;
    float o3 = (v.w-mu)*inv*g.w + bt.w;
    size_t base = (size_t)row*DD + tid*4;
    *(__half2*)&Ah[base]   = __halves2half2(__float2half_rn(o0), __float2half_rn(o1));
    *(__half2*)&Ah[base+2] = __halves2half2(__float2half_rn(o2), __float2half_rn(o3));
}

// ---------------- Weight prep ----------------
__global__ void prep_w_kernel(const float* __restrict__ W, __half* __restrict__ Bp,
                              int K, int N) {
    __shared__ float ts[32][33];
    const int n0 = blockIdx.x*32, k0 = blockIdx.y*32;
    const int tx = threadIdx.x, ty = threadIdx.y;   // (32,8)
    #pragma unroll
    for (int i = 0; i < 4; i++)
        ts[ty+8*i][tx] = W[(size_t)(k0+ty+8*i)*N + n0+tx];
    __syncthreads();
    #pragma unroll
    for (int i = 0; i < 4; i++) {
        int nl = ty + 8*i;
        Bp[(size_t)(n0+nl)*K + k0+tx] = __float2half_rn(ts[tx][nl]);
    }
}

// ---------------- mma.sync fp16 GEMM ----------------
#define GBK 64
#define NSTG 3
#define STB 16384
#define STAGE_BYTES (2*STB)
#define HG_SMEM (NSTG*STAGE_BYTES)

__global__ __launch_bounds__(256, 2) void hgemm_kernel(
    const __half* __restrict__ Ah, const __half* __restrict__ Bp,
    const float* __restrict__ bias, const float* __restrict__ add,
    float* __restrict__ C, __half* __restrict__ Cah,
    int M, int N, int ldc, int K, int act, int splitOut)
{
    extern __shared__ char dsm[];
    const uint32_t sb = smem_u32(dsm);
    const int tid = threadIdx.x;
    const int lane = tid & 31, wid = tid >> 5;
    const int row0 = blockIdx.y * 128, col0 = blockIdx.x * 128;
    const int NT = K / GBK;

    const int wm = (wid >> 2) * 64;
    const int wn = (wid & 3) * 32;

    float acc[4][4][4];
    #pragma unroll
    for (int i=0;i<4;i++)
        #pragma unroll
        for (int j=0;j<4;j++)
            #pragma unroll
            for (int c=0;c<4;c++) acc[i][j][c]=0.f;

    auto load_tile = [&](int t, int s) {
        int k0 = t * GBK;
        uint32_t stA = sb + s*STAGE_BYTES;
        uint32_t stB = stA + STB;
        #pragma unroll
        for (int i = 0; i < 4; i++) {
            int ch = i*256 + tid;
            int r = ch >> 3, c = (ch & 7) * 8;
            cpa16(stA + SWZ(ch*16), Ah + (size_t)(row0 + r)*K + k0 + c);
            cpa16(stB + SWZ(ch*16), Bp + (size_t)(col0 + r)*K + k0 + c);
        }
        asm volatile("cp.async.commit_group;" ::: "memory");
    };

    load_tile(0, 0);
    if (NT > 1) load_tile(1, 1);

    const int aRow = wm + (lane & 15);
    const int aColB = ((lane >> 4) & 1) * 16;
    const int bRow = wn + (lane & 7) + ((lane >> 4) & 1) * 8;
    const int bColB = ((lane >> 3) & 1) * 16;

    for (int t = 0; t < NT; t++) {
        if (t < NT-1) asm volatile("cp.async.wait_group 1;" ::: "memory");
        else          asm volatile("cp.async.wait_group 0;" ::: "memory");
        __syncthreads();
        if (t + 2 < NT) load_tile(t + 2, (t + 2) % NSTG);
        uint32_t stA = sb + (t % NSTG)*STAGE_BYTES;
        uint32_t stB = stA + STB;
        #pragma unroll
        for (int kk = 0; kk < 4; kk++) {
            uint32_t af[4][4];
            #pragma unroll
            for (int mt = 0; mt < 4; mt++) {
                uint32_t addr = stA + SWZ((uint32_t)(aRow + mt*16)*128 + kk*32 + aColB);
                LDSM4(af[mt][0], af[mt][1], af[mt][2], af[mt][3], addr);
            }
            uint32_t bf[4][2];
            #pragma unroll
            for (int nt2 = 0; nt2 < 2; nt2++) {
                uint32_t r0,r1,r2,r3;
                uint32_t addr = stB + SWZ((uint32_t)(bRow + nt2*16)*128 + kk*32 + bColB);
                LDSM4(r0, r1, r2, r3, addr);
                bf[nt2*2][0]=r0; bf[nt2*2][1]=r1; bf[nt2*2+1][0]=r2; bf[nt2*2+1][1]=r3;
            }
            #pragma unroll
            for (int mt = 0; mt < 4; mt++)
                #pragma unroll
                for (int nt = 0; nt < 4; nt++)
                    MMA16816(acc[mt][nt], af[mt], bf[nt]);
        }
        __syncthreads();
    }

    const int erow = lane >> 2, ecol = (lane & 3) * 2;
    #pragma unroll
    for (int mt = 0; mt < 4; mt++) {
        #pragma unroll
        for (int half_ = 0; half_ < 2; half_++) {
            int row = row0 + wm + mt*16 + erow + half_*8;
            size_t rbase = (size_t)row * ldc;
            #pragma unroll
            for (int nt = 0; nt < 4; nt++) {
                int col = col0 + wn + nt*8 + ecol;
                float v0 = acc[mt][nt][half_*2+0];
                float v1 = acc[mt][nt][half_*2+1];
                if (bias) { v0 += bias[col]; v1 += bias[col+1]; }
                if (act)  { v0 = gelu_f(v0); v1 = gelu_f(v1); }
                if (add)  {
                    const float2 a2 = *(const float2*)&add[rbase + col];
                    v0 += a2.x; v1 += a2.y;
                }
                if (splitOut) {
                    *(__half2*)&Cah[rbase + col] =
                        __halves2half2(__float2half_rn(v0), __float2half_rn(v1));
                } else {
                    *(float2*)&C[rbase + col] = make_float2(v0, v1);
                }
            }
        }
    }
}

// 8 halves (uint4) -> two float4
__device__ __forceinline__ void h8_to_f8(uint4 u, float4& lo, float4& hi) {
    __half2* h = (__half2*)&u;
    float2 f0 = __half22float2(h[0]);
    float2 f1 = __half22float2(h[1]);
    float2 f2 = __half22float2(h[2]);
    float2 f3 = __half22float2(h[3]);
    lo = make_float4(f0.x, f0.y, f1.x, f1.y);
    hi = make_float4(f2.x, f2.y, f3.x, f3.y);
}

// ---------------- Per-segment partial memory contributions ----------------
__global__ void segkv_kernel(const __half* __restrict__ k, const __half* __restrict__ v,
                             float* __restrict__ msp, float* __restrict__ zsp)
{
    __shared__ float sks[32][128];
    __shared__ float svs[32][128];
    __shared__ float zacc[128];
    const int seg = blockIdx.x, bh = blockIdx.y, ch = blockIdx.z;
    const int b = bh >> 3, h = bh & 7;
    const int tid = threadIdx.x;
    const int ty = tid >> 4, tx = tid & 15;
    float acc[8][8];
    #pragma unroll
    for (int i=0;i<8;i++)
        #pragma unroll
        for (int j=0;j<8;j++) acc[i][j]=0.f;
    if (tid < 128) zacc[tid] = 0.f;
    size_t base = ((size_t)b*SS + seg*SEG_ + ch*128)*QS + h*DK_;
    for (int p0 = 0; p0 < 128; p0 += 32) {
        __syncthreads();
        for (int i = tid; i < 512; i += 256) {
            int row = i >> 4, c8 = (i & 15)*8;
            uint4 ku = *(const uint4*)&k[base + (size_t)(p0+row)*QS + c8];
            float4 klo, khi;
            h8_to_f8(ku, klo, khi);
            klo.x = klo.x>0.f?klo.x+1.f:__expf(klo.x);
            klo.y = klo.y>0.f?klo.y+1.f:__expf(klo.y);
            klo.z = klo.z>0.f?klo.z+1.f:__expf(klo.z);
            klo.w = klo.w>0.f?klo.w+1.f:__expf(klo.w);
            khi.x = khi.x>0.f?khi.x+1.f:__expf(khi.x);
            khi.y = khi.y>0.f?khi.y+1.f:__expf(khi.y);
            khi.z = khi.z>0.f?khi.z+1.f:__expf(khi.z);
            khi.w = khi.w>0.f?khi.w+1.f:__expf(khi.w);
            *(float4*)&sks[row][c8]   = klo;
            *(float4*)&sks[row][c8+4] = khi;
            uint4 vu = *(const uint4*)&v[base + (size_t)(p0+row)*QS + c8];
            float4 vlo, vhi;
            h8_to_f8(vu, vlo, vhi);
            *(float4*)&svs[row][c8]   = vlo;
            *(float4*)&svs[row][c8+4] = vhi;
        }
        __syncthreads();
        if (tid < 128) {
            float za = 0.f;
            for (int p = 0; p < 32; p++) za += sks[p][tid];
            zacc[tid] += za;
        }
        #pragma unroll 4
        for (int p = 0; p < 32; p++) {
            float4 k0 = *(const float4*)&sks[p][ty*8];
            float4 k1 = *(const float4*)&sks[p][ty*8+4];
            float4 v0 = *(const float4*)&svs[p][tx*8];
            float4 v1 = *(const float4*)&svs[p][tx*8+4];
            float kr[8] = {k0.x,k0.y,k0.z,k0.w,k1.x,k1.y,k1.z,k1.w};
            float vr[8] = {v0.x,v0.y,v0.z,v0.w,v1.x,v1.y,v1.z,v1.w};
            #pragma unroll
            for (int i=0;i<8;i++)
                #pragma unroll
                for (int j=0;j<8;j++) acc[i][j] += kr[i]*vr[j];
        }
    }
    const int slice = seg*NCH + ch;
    size_t obase = ((size_t)slice*32 + bh)*DK_*DK_;
    #pragma unroll
    for (int i=0;i<8;i++)
        #pragma unroll
        for (int j=0;j<8;j++)
            msp[obase + (size_t)(ty*8+i)*DK_ + tx*8+j] = acc[i][j];
    if (tid < 128) zsp[((size_t)slice*32 + bh)*DK_ + tid] = zacc[tid];
}

// ---------------- Exclusive prefix over 8 segments -> fp16 M, fp32 z ----------------
__global__ void prefix_kernel(const float* __restrict__ msp, const float* __restrict__ zsp,
                              __half* __restrict__ mph, float* __restrict__ zp)
{
    size_t idx = (size_t)blockIdx.x*256 + threadIdx.x;
    const size_t stride = (size_t)BB*HH*DK_*DK_;
    if (idx < stride) {
        float a = 0.f;
        #pragma unroll
        for (int t = 0; t < NSEG; t++) {
            mph[t*stride + idx] = __float2half_rn(a);
            #pragma unroll
            for (int c = 0; c < NCH; c++)
                a += msp[(size_t)(t*NCH + c)*stride + idx];
        }
    }
    if (idx < (size_t)BB*HH*DK_) {
        const size_t zstr = (size_t)BB*HH*DK_;
        float a = 1.f/128.f;
        #pragma unroll
        for (int t = 0; t < NSEG; t++) {
            zp[t*zstr + idx] = a;
            #pragma unroll
            for (int c = 0; c < NCH; c++)
                a += zsp[(size_t)(t*NCH + c)*zstr + idx];
        }
    }
}

// ---------------- Tensor-core attention (FA2-style) ----------------
// smem layout (bytes): Qh 0..16K, Kh 16K..32K, Vh 32K..48K (Kh+Vh reused for M 32KB),
// Ph 48K..56K (reused for sqh 48K..64K), Sf 56K..73K, stats 73K..74.5K
#define SM_QH   0
#define SM_KH   16384
#define SM_VH   32768
#define SM_PH   49152
#define SM_SQH  49152
#define SM_MH   16384
#define SM_SF   57344
#define SM_ST   74752
#define ATTN_SMEM (SM_ST + 1536)

__global__ __launch_bounds__(256, 1) void attn_kernel(
    const __half* __restrict__ q, const __half* __restrict__ k,
    const __half* __restrict__ v, const __half* __restrict__ mph,
    const float* __restrict__ zp, const float* __restrict__ betas,
    __half* __restrict__ Oah)
{
    extern __shared__ char sm[];
    const uint32_t base = smem_u32(sm);
    float* Sf   = (float*)(sm + SM_SF);       // [64][68]
    float* Zs   = (float*)(sm + SM_ST);       // 128
    float* mrow = Zs + 128;
    float* lrow = mrow + 64;
    float* arow = lrow + 64;
    float* drow = arow + 64;

    const int qt = blockIdx.x, seg = blockIdx.y;
    const int b = blockIdx.z >> 3, h = blockIdx.z & 7;
    const int tid = threadIdx.x;
    const int lane = tid & 31, wid = tid >> 5;
    const int wmS = (wid >> 2) * 32, wnS = (wid & 3) * 16;
    const int wmP = (wid >> 2) * 32, wnP = (wid & 3) * 32;

    const float* Z = zp + (((size_t)seg*BB + b)*HH + h)*DK_;
    size_t qbase = ((size_t)b*SS + seg*SEG_ + qt*64)*QS + h*DK_;
    // load Q (fp16, swizzled)
    #pragma unroll
    for (int ch = tid; ch < 1024; ch += 256) {
        int row = ch >> 4, c16 = ch & 15;
        *(uint4*)&sm[SM_QH + SWZ(ch*16)] = *(const uint4*)&q[qbase + (size_t)row*QS + c16*8];
    }
    if (tid < 128) Zs[tid] = Z[tid];
    if (tid < 64) { mrow[tid] = -INFINITY; lrow[tid] = 0.f; }

    float acc_o[2][4][4];
    #pragma unroll
    for (int i=0;i<2;i++)
        #pragma unroll
        for (int j=0;j<4;j++)
            #pragma unroll
            for (int c=0;c<4;c++) acc_o[i][j][c]=0.f;

    const float scale = 0.08838834764831845f;
    for (int kt = 0; kt <= qt; kt++) {
        __syncthreads();   // prev PV done; safe to overwrite Kh/Vh
        size_t kbase = ((size_t)b*SS + seg*SEG_ + kt*64)*QS + h*DK_;
        #pragma unroll
        for (int ch = tid; ch < 1024; ch += 256) {
            int row = ch >> 4, c16 = ch & 15;
            *(uint4*)&sm[SM_KH + SWZ(ch*16)] = *(const uint4*)&k[kbase + (size_t)row*QS + c16*8];
            *(uint4*)&sm[SM_VH + SWZ(ch*16)] = *(const uint4*)&v[kbase + (size_t)row*QS + c16*8];
        }
        __syncthreads();

        // S = Q K^T
        float accs[2][2][4];
        #pragma unroll
        for (int i=0;i<2;i++)
            #pragma unroll
            for (int j=0;j<2;j++)
                #pragma unroll
                for (int c=0;c<4;c++) accs[i][j][c]=0.f;
        #pragma unroll
        for (int kk = 0; kk < 8; kk++) {
            int eA = kk*16 + ((lane>>4)&1)*8;
            uint32_t af[2][4];
            #pragma unroll
            for (int mt = 0; mt < 2; mt++)
                LDSM4(af[mt][0],af[mt][1],af[mt][2],af[mt][3],
                      base + SM_QH + swz256(wmS + mt*16 + (lane&15), eA));
            int eB = kk*16 + ((lane>>3)&1)*8;
            uint32_t b0,b1,b2,b3;
            LDSM4(b0,b1,b2,b3,
                  base + SM_KH + swz256(wnS + (lane&7) + ((lane>>4)&1)*8, eB));
            uint32_t bf[2][2] = {{b0,b1},{b2,b3}};
            #pragma unroll
            for (int mt = 0; mt < 2; mt++)
                #pragma unroll
                for (int nt = 0; nt < 2; nt++)
                    MMA16816(accs[mt][nt], af[mt], bf[nt]);
        }
        // store S (scaled+masked) to Sf
        #pragma unroll
        for (int mt = 0; mt < 2; mt++)
            #pragma unroll
            for (int nt = 0; nt < 2; nt++)
                #pragma unroll
                for (int c = 0; c < 4; c++) {
                    int r = wmS + mt*16 + (lane>>2) + ((c>>1)&1)*8;
                    int cc = wnS + nt*8 + (lane&3)*2 + (c&1);
                    float vv = accs[mt][nt][c]*scale;
                    if (kt == qt && cc > r) vv = -INFINITY;
                    Sf[r*68 + cc] = vv;
                }
        __syncthreads();

        // softmax: 4 lanes per row
        {
            int r = tid >> 2, qd = tid & 3;
            float v16[16];
            float mx = -INFINITY;
            #pragma unroll
            for (int i = 0; i < 16; i++) {
                v16[i] = Sf[r*68 + qd*16 + i];
                mx = fmaxf(mx, v16[i]);
            }
            mx = fmaxf(mx, __shfl_xor_sync(0xffffffffu, mx, 1));
            mx = fmaxf(mx, __shfl_xor_sync(0xffffffffu, mx, 2));
            float mold = mrow[r];
            float mnew = fmaxf(mold, mx);
            float al = __expf(mold - mnew);
            float ps = 0.f;
            #pragma unroll
            for (int i = 0; i < 16; i += 2) {
                float p0 = __expf(v16[i]   - mnew);
                float p1 = __expf(v16[i+1] - mnew);
                ps += p0 + p1;
                *(__half2*)&sm[SM_PH + SWZ((uint32_t)(r*128 + (qd*16+i)*2))] =
                    __halves2half2(__float2half_rn(p0), __float2half_rn(p1));
            }
            ps += __shfl_xor_sync(0xffffffffu, ps, 1);
            ps += __shfl_xor_sync(0xffffffffu, ps, 2);
            if (qd == 0) {
                lrow[r] = lrow[r]*al + ps;
                mrow[r] = mnew;
                arow[r] = al;
            }
        }
        __syncthreads();

        // rescale + PV
        float alv[2][2];
        #pragma unroll
        for (int mt = 0; mt < 2; mt++)
            #pragma unroll
            for (int hh = 0; hh < 2; hh++)
                alv[mt][hh] = arow[wmP + mt*16 + (lane>>2) + hh*8];
        #pragma unroll
        for (int mt = 0; mt < 2; mt++)
            #pragma unroll
            for (int nt = 0; nt < 4; nt++)
                #pragma unroll
                for (int c = 0; c < 4; c++)
                    acc_o[mt][nt][c] *= alv[mt][(c>>1)&1];
        #pragma unroll
        for (int kk2 = 0; kk2 < 4; kk2++) {
            int eA = kk2*16 + ((lane>>4)&1)*8;
            uint32_t af[2][4];
            #pragma unroll
            for (int mt = 0; mt < 2; mt++)
                LDSM4(af[mt][0],af[mt][1],af[mt][2],af[mt][3],
                      base + SM_PH + swz128(wmP + mt*16 + (lane&15), eA));
            uint32_t bf[4][2];
            #pragma unroll
            for (int ntp = 0; ntp < 2; ntp++) {
                int krow = kk2*16 + (lane&15);
                int n = wnP + ntp*16 + ((lane>>4)&1)*8;
                uint32_t r0,r1,r2,r3;
                LDSM4T(r0,r1,r2,r3, base + SM_VH + swz256(krow, n));
                bf[ntp*2][0]=r0; bf[ntp*2][1]=r1; bf[ntp*2+1][0]=r2; bf[ntp*2+1][1]=r3;
            }
            #pragma unroll
            for (int mt = 0; mt < 2; mt++)
                #pragma unroll
                for (int nt = 0; nt < 4; nt++)
                    MMA16816(acc_o[mt][nt], af[mt], bf[nt]);
        }
    }
    __syncthreads();   // PV done; Ph/Sf/Kh/Vh reusable

    // build sqh = elu(q)+1 (fp16) ; load M (fp16) into Kh+Vh region
    #pragma unroll
    for (int ch = tid; ch < 1024; ch += 256) {
        uint4 u = *(const uint4*)&sm[SM_QH + SWZ(ch*16)];
        __half2* hp = (__half2*)&u;
        #pragma unroll
        for (int t = 0; t < 4; t++) {
            float2 f = __half22float2(hp[t]);
            f.x = f.x > 0.f ? f.x + 1.f : __expf(f.x);
            f.y = f.y > 0.f ? f.y + 1.f : __expf(f.y);
            hp[t] = __halves2half2(__float2half_rn(f.x), __float2half_rn(f.y));
        }
        *(uint4*)&sm[SM_SQH + SWZ(ch*16)] = u;
    }
    const __half* M = mph + (((size_t)seg*BB + b)*HH + h)*DK_*DK_;
    #pragma unroll
    for (int ch = tid; ch < 2048; ch += 256)
        *(uint4*)&sm[SM_MH + SWZ(ch*16)] = *(const uint4*)&M[(size_t)ch*8];
    __syncthreads();

    // ds = sq . Z (fp32, from fp16-rounded sq for consistency)
    {
        int r = tid >> 2, qd = tid & 3;
        float ds = 0.f;
        #pragma unroll
        for (int j = 0; j < 4; j++) {
            int e = qd*32 + j*8;
            uint4 u = *(const uint4*)&sm[SM_SQH + swz256(r, e)];
            float4 lo, hi;
            h8_to_f8(u, lo, hi);
            const float4 z0 = *(const float4*)&Zs[e];
            const float4 z1 = *(const float4*)&Zs[e+4];
            ds += lo.x*z0.x + lo.y*z0.y + lo.z*z0.z + lo.w*z0.w
                + hi.x*z1.x + hi.y*z1.y + hi.z*z1.z + hi.w*z1.w;
        }
        ds += __shfl_xor_sync(0xffffffffu, ds, 1);
        ds += __shfl_xor_sync(0xffffffffu, ds, 2);
        if (qd == 0) drow[r] = ds;
    }
    __syncthreads();

    // retrieval: am = sq @ M  (mma)
    float acc_m[2][4][4];
    #pragma unroll
    for (int i=0;i<2;i++)
        #pragma unroll
        for (int j=0;j<4;j++)
            #pragma unroll
            for (int c=0;c<4;c++) acc_m[i][j][c]=0.f;
    #pragma unroll
    for (int kk = 0; kk < 8; kk++) {
        int eA = kk*16 + ((lane>>4)&1)*8;
        uint32_t af[2][4];
        #pragma unroll
        for (int mt = 0; mt < 2; mt++)
            LDSM4(af[mt][0],af[mt][1],af[mt][2],af[mt][3],
                  base + SM_SQH + swz256(wmP + mt*16 + (lane&15), eA));
        uint32_t bf[4][2];
        #pragma unroll
        for (int ntp = 0; ntp < 2; ntp++) {
            int d = kk*16 + (lane&15);
            int n = wnP + ntp*16 + ((lane>>4)&1)*8;
            uint32_t r0,r1,r2,r3;
            LDSM4T(r0,r1,r2,r3, base + SM_MH + swz256(d, n));
            bf[ntp*2][0]=r0; bf[ntp*2][1]=r1; bf[ntp*2+1][0]=r2; bf[ntp*2+1][1]=r3;
        }
        #pragma unroll
        for (int mt = 0; mt < 2; mt++)
            #pragma unroll
            for (int nt = 0; nt < 4; nt++)
                MMA16816(acc_m[mt][nt], af[mt], bf[nt]);
    }

    // gate + write fp16 output
    #pragma unroll
    for (int mt = 0; mt < 2; mt++) {
        #pragma unroll
        for (int hh = 0; hh < 2; hh++) {
            int row = wmP + mt*16 + (lane>>2) + hh*8;
            float dinv = 1.f / drow[row];
            float linv = 1.f / lrow[row];
            size_t ob = ((size_t)b*SS + seg*SEG_ + qt*64 + row)*DD + h*DK_;
            #pragma unroll
            for (int nt = 0; nt < 4; nt++) {
                int col = wnP + nt*8 + (lane&3)*2;
                float g0 = 1.f / (1.f + __expf(-betas[h*DK_ + col]));
                float g1 = 1.f / (1.f + __expf(-betas[h*DK_ + col + 1]));
                float u0 = g0*(acc_m[mt][nt][hh*2]  *dinv) + (1.f-g0)*(acc_o[mt][nt][hh*2]  *linv);
                float u1 = g1*(acc_m[mt][nt][hh*2+1]*dinv) + (1.f-g1)*(acc_o[mt][nt][hh*2+1]*linv);
                *(__half2*)&Oah[ob + col] = __halves2half2(__float2half_rn(u0), __float2half_rn(u1));
            }
        }
    }
}

// ---------------- launch ----------------
extern "C" void kernel_launch(void* const* d_in, const int* in_sizes, int n_in,
                              void* d_out, int out_size)
{
    const float* x     = (const float*)d_in[0];
    const float* ln_g  = (const float*)d_in[1];
    const float* ln_b  = (const float*)d_in[2];
    const float* Wq    = (const float*)d_in[3];
    const float* Wk    = (const float*)d_in[4];
    const float* Wv    = (const float*)d_in[5];
    const float* Wo    = (const float*)d_in[6];
    const float* betas = (const float*)d_in[7];
    const float* w1    = (const float*)d_in[8];
    const float* b1    = (const float*)d_in[9];
    const float* w2    = (const float*)d_in[10];
    const float* b2    = (const float*)d_in[11];
    float* out = (float*)d_out;

    float *x1, *ff, *msp, *zsp, *zp;
    __half *qkvh, *mph, *ah, *bqkv, *bo, *bw1, *bw2;
    cudaGetSymbolAddress((void**)&qkvh, g_qkvh);
    cudaGetSymbolAddress((void**)&x1, g_x1);
    cudaGetSymbolAddress((void**)&ff, g_ff);
    cudaGetSymbolAddress((void**)&msp, g_msp);
    cudaGetSymbolAddress((void**)&mph, g_mph);
    cudaGetSymbolAddress((void**)&zsp, g_zsp);
    cudaGetSymbolAddress((void**)&zp, g_zp);
    cudaGetSymbolAddress((void**)&ah, g_ah);
    cudaGetSymbolAddress((void**)&bqkv, g_bqkv);
    cudaGetSymbolAddress((void**)&bo, g_bo);
    cudaGetSymbolAddress((void**)&bw1, g_bw1);
    cudaGetSymbolAddress((void**)&bw2, g_bw2);

    __half* ah2 = (__half*)ff;     // FFN1 hi-only output

    cudaFuncSetAttribute(attn_kernel, cudaFuncAttributeMaxDynamicSharedMemorySize, ATTN_SMEM);
    cudaFuncSetAttribute(hgemm_kernel, cudaFuncAttributeMaxDynamicSharedMemorySize, HG_SMEM);

    dim3 wblk(32, 8);

    // weight prep
    prep_w_kernel<<<dim3(1024/32, 1024/32), wblk>>>(Wq, bqkv,                      1024, 1024);
    prep_w_kernel<<<dim3(1024/32, 1024/32), wblk>>>(Wk, bqkv + (size_t)1024*1024,  1024, 1024);
    prep_w_kernel<<<dim3(1024/32, 1024/32), wblk>>>(Wv, bqkv + (size_t)2048*1024,  1024, 1024);
    prep_w_kernel<<<dim3(1024/32, 1024/32), wblk>>>(Wo, bo, 1024, 1024);
    prep_w_kernel<<<dim3(4096/32, 1024/32), wblk>>>(w1, bw1, 1024, 4096);
    prep_w_kernel<<<dim3(1024/32, 4096/32), wblk>>>(w2, bw2, 4096, 1024);

    // 1) LN1 -> fp16
    ln_kernel<<<MROWS, 256>>>(x, ln_g, ln_b, ah);
    // 2) fused QKV projection -> fp16 qkv
    hgemm_kernel<<<dim3(QS/128, MROWS/128), 256, HG_SMEM>>>(ah, bqkv, nullptr, nullptr,
                                                            nullptr, qkvh, MROWS, QS, QS, DD, 0, 2);
    // 3-5) infini-attention
    segkv_kernel<<<dim3(NSEG, BB*HH, NCH), 256>>>(qkvh + 1024, qkvh + 2048, msp, zsp);
    prefix_kernel<<<(BB*HH*DK_*DK_)/256, 256>>>(msp, zsp, mph, zp);
    attn_kernel<<<dim3(8, NSEG, BB*HH), 256, ATTN_SMEM>>>(qkvh, qkvh + 1024, qkvh + 2048,
                                                          mph, zp, betas, ah);
    // 6) output projection + residual
    dim3 g1(DD/128, MROWS/128);
    hgemm_kernel<<<g1, 256, HG_SMEM>>>(ah, bo, nullptr, x, x1, nullptr,
                                       MROWS, DD, DD, DD, 0, 0);
    // 7) LN2 -> fp16
    ln_kernel<<<MROWS, 256>>>(x1, ln_g, ln_b, ah);
    // 8) FFN1 + bias + gelu -> fp16
    hgemm_kernel<<<dim3(DH_/128, MROWS/128), 256, HG_SMEM>>>(ah, bw1, b1, nullptr, nullptr,
                                                             ah2, MROWS, DH_, DH_, DD, 1, 2);
    // 9) FFN2 + bias + residual -> out
    hgemm_kernel<<<dim3(DD/128, MROWS/128), 256, HG_SMEM>>>(ah2, bw2, b2, x1, out,
                                                            nullptr, MROWS, DD, DD, DH_, 0, 0);
}

// round 14
// speedup vs baseline: 1.7070x; 1.0641x over previous
#include <cuda_runtime.h>
#include <cuda_fp16.h>
#include <math.h>
#include <stdint.h>

// Problem constants
#define BB   4
#define SS   4096
#define DD   1024
#define HH   8
#define DK_  128
#define SEG_ 512
#define NSEG 8
#define DH_  4096
#define MROWS (BB*SS)   // 16384
#define QS   3072       // fused qkv row stride
#define NCH  4          // segkv position chunks per segment

// ---------------- scratch ----------------
__device__ __half g_qkvh[(size_t)MROWS*QS];            // fp16 q|k|v
__device__ float g_x1[(size_t)MROWS*DD];
__device__ float g_ff[(size_t)MROWS*DH_];              // reused: FFN1 hi fp16 output
__device__ float g_msp[(size_t)NSEG*NCH*BB*HH*DK_*DK_]; // partial seg outer products
__device__ __half g_mph[(size_t)NSEG*BB*HH*DK_*DK_];    // fp16 prefix memory
__device__ float g_zsp[(size_t)NSEG*NCH*BB*HH*DK_];
__device__ float g_zp [(size_t)NSEG*BB*HH*DK_];
// fp16 activation buffer [M][1024] (hi only)
__device__ __half g_ah[(size_t)MROWS*DD];
// transposed fp16 weights [N][K]
__device__ __half g_bqkv[(size_t)QS*DD];
__device__ __half g_bo[(size_t)DD*DD];
__device__ __half g_bw1[(size_t)DH_*DD];
__device__ __half g_bw2[(size_t)DD*DH_];

__device__ __forceinline__ float gelu_f(float x) {
    float x3 = x*x*x;
    float t = tanhf(0.7978845608028654f*(x + 0.044715f*x3));
    return 0.5f*x*(1.f + t);
}

// ================= PTX helpers =================
__device__ __forceinline__ uint32_t smem_u32(const void* p) {
    uint32_t a;
    asm("{ .reg .u64 t; cvta.to.shared.u64 t, %1; cvt.u32.u64 %0, t; }" : "=r"(a) : "l"(p));
    return a;
}
__device__ __forceinline__ void cpa16(uint32_t d, const void* s) {
    asm volatile("cp.async.cg.shared.global [%0], [%1], 16;"
                 :: "r"(d), "l"(__cvta_generic_to_global((void*)s)) : "memory");
}
#define SWZ(x) ((x) ^ (((x) >> 3) & 0x70))

#define LDSM4(r0,r1,r2,r3,addr) \
    asm volatile("ldmatrix.sync.aligned.m8n8.x4.shared.b16 {%0,%1,%2,%3}, [%4];" \
                 : "=r"(r0),"=r"(r1),"=r"(r2),"=r"(r3) : "r"(addr))

#define LDSM4T(r0,r1,r2,r3,addr) \
    asm volatile("ldmatrix.sync.aligned.m8n8.x4.trans.shared.b16 {%0,%1,%2,%3}, [%4];" \
                 : "=r"(r0),"=r"(r1),"=r"(r2),"=r"(r3) : "r"(addr))

#define MMA16816(d, a, b) \
    asm volatile("mma.sync.aligned.m16n8k16.row.col.f32.f16.f16.f32 " \
                 "{%0,%1,%2,%3}, {%4,%5,%6,%7}, {%8,%9}, {%0,%1,%2,%3};" \
                 : "+f"((d)[0]),"+f"((d)[1]),"+f"((d)[2]),"+f"((d)[3]) \
                 : "r"((a)[0]),"r"((a)[1]),"r"((a)[2]),"r"((a)[3]), \
                   "r"((b)[0]),"r"((b)[1]))

// swizzled byte offsets: 256B-pitch rows (128 fp16) and 128B-pitch rows (64 fp16)
__device__ __forceinline__ uint32_t swz256(int row, int e) {
    return SWZ((uint32_t)((row*2 + (e>>6))*128 + (e&63)*2));
}
__device__ __forceinline__ uint32_t swz128(int row, int e) {
    return SWZ((uint32_t)(row*128 + e*2));
}

// ---------------- LayerNorm -> fp16 (hi only) ----------------
__global__ void ln_kernel(const float* __restrict__ x, const float* __restrict__ gamma,
                          const float* __restrict__ beta, __half* __restrict__ Ah) {
    __shared__ float s1[256], s2[256];
    const int row = blockIdx.x;
    const int tid = threadIdx.x;
    const float* xr = x + (size_t)row*DD;
    float4 v = *(const float4*)&xr[tid*4];
    float s  = v.x+v.y+v.z+v.w;
    float ss = v.x*v.x+v.y*v.y+v.z*v.z+v.w*v.w;
    s1[tid]=s; s2[tid]=ss; __syncthreads();
    for (int o=128;o>0;o>>=1){ if(tid<o){s1[tid]+=s1[tid+o]; s2[tid]+=s2[tid+o];} __syncthreads(); }
    float mu  = s1[0]*(1.f/DD);
    float var = s2[0]*(1.f/DD) - mu*mu;
    float inv = rsqrtf(var + 1e-5f);
    float4 g  = *(const float4*)&gamma[tid*4];
    float4 bt = *(const float4*)&beta[tid*4];
    float o0 = (v.x-mu)*inv*g.x + bt.x;
    float o1 = (v.y-mu)*inv*g.y + bt.y;
    float o2 = (v.z-mu)*inv*g.z + bt.z;
    float o3 = (v.w-mu)*inv*g.w + bt.w;
    size_t base = (size_t)row*DD + tid*4;
    *(__half2*)&Ah[base]   = __halves2half2(__float2half_rn(o0), __float2half_rn(o1));
    *(__half2*)&Ah[base+2] = __halves2half2(__float2half_rn(o2), __float2half_rn(o3));
}

// ---------------- Weight prep ----------------
__global__ void prep_w_kernel(const float* __restrict__ W, __half* __restrict__ Bp,
                              int K, int N) {
    __shared__ float ts[32][33];
    const int n0 = blockIdx.x*32, k0 = blockIdx.y*32;
    const int tx = threadIdx.x, ty = threadIdx.y;   // (32,8)
    #pragma unroll
    for (int i = 0; i < 4; i++)
        ts[ty+8*i][tx] = W[(size_t)(k0+ty+8*i)*N + n0+tx];
    __syncthreads();
    #pragma unroll
    for (int i = 0; i < 4; i++) {
        int nl = ty + 8*i;
        Bp[(size_t)(n0+nl)*K + k0+tx] = __float2half_rn(ts[tx][nl]);
    }
}

// ---------------- mma.sync fp16 GEMM ----------------
#define GBK 64
#define NSTG 3
#define STB 16384
#define STAGE_BYTES (2*STB)
#define HG_SMEM (NSTG*STAGE_BYTES)

__global__ __launch_bounds__(256, 2) void hgemm_kernel(
    const __half* __restrict__ Ah, const __half* __restrict__ Bp,
    const float* __restrict__ bias, const float* __restrict__ add,
    float* __restrict__ C, __half* __restrict__ Cah,
    int M, int N, int ldc, int K, int act, int splitOut)
{
    extern __shared__ char dsm[];
    const uint32_t sb = smem_u32(dsm);
    const int tid = threadIdx.x;
    const int lane = tid & 31, wid = tid >> 5;
    const int row0 = blockIdx.y * 128, col0 = blockIdx.x * 128;
    const int NT = K / GBK;

    const int wm = (wid >> 2) * 64;
    const int wn = (wid & 3) * 32;

    float acc[4][4][4];
    #pragma unroll
    for (int i=0;i<4;i++)
        #pragma unroll
        for (int j=0;j<4;j++)
            #pragma unroll
            for (int c=0;c<4;c++) acc[i][j][c]=0.f;

    auto load_tile = [&](int t, int s) {
        int k0 = t * GBK;
        uint32_t stA = sb + s*STAGE_BYTES;
        uint32_t stB = stA + STB;
        #pragma unroll
        for (int i = 0; i < 4; i++) {
            int ch = i*256 + tid;
            int r = ch >> 3, c = (ch & 7) * 8;
            cpa16(stA + SWZ(ch*16), Ah + (size_t)(row0 + r)*K + k0 + c);
            cpa16(stB + SWZ(ch*16), Bp + (size_t)(col0 + r)*K + k0 + c);
        }
        asm volatile("cp.async.commit_group;" ::: "memory");
    };

    load_tile(0, 0);
    if (NT > 1) load_tile(1, 1);

    const int aRow = wm + (lane & 15);
    const int aColB = ((lane >> 4) & 1) * 16;
    const int bRow = wn + (lane & 7) + ((lane >> 4) & 1) * 8;
    const int bColB = ((lane >> 3) & 1) * 16;

    for (int t = 0; t < NT; t++) {
        if (t < NT-1) asm volatile("cp.async.wait_group 1;" ::: "memory");
        else          asm volatile("cp.async.wait_group 0;" ::: "memory");
        __syncthreads();
        if (t + 2 < NT) load_tile(t + 2, (t + 2) % NSTG);
        uint32_t stA = sb + (t % NSTG)*STAGE_BYTES;
        uint32_t stB = stA + STB;
        #pragma unroll
        for (int kk = 0; kk < 4; kk++) {
            uint32_t af[4][4];
            #pragma unroll
            for (int mt = 0; mt < 4; mt++) {
                uint32_t addr = stA + SWZ((uint32_t)(aRow + mt*16)*128 + kk*32 + aColB);
                LDSM4(af[mt][0], af[mt][1], af[mt][2], af[mt][3], addr);
            }
            uint32_t bf[4][2];
            #pragma unroll
            for (int nt2 = 0; nt2 < 2; nt2++) {
                uint32_t r0,r1,r2,r3;
                uint32_t addr = stB + SWZ((uint32_t)(bRow + nt2*16)*128 + kk*32 + bColB);
                LDSM4(r0, r1, r2, r3, addr);
                bf[nt2*2][0]=r0; bf[nt2*2][1]=r1; bf[nt2*2+1][0]=r2; bf[nt2*2+1][1]=r3;
            }
            #pragma unroll
            for (int mt = 0; mt < 4; mt++)
                #pragma unroll
                for (int nt = 0; nt < 4; nt++)
                    MMA16816(acc[mt][nt], af[mt], bf[nt]);
        }
        __syncthreads();
    }

    const int erow = lane >> 2, ecol = (lane & 3) * 2;
    #pragma unroll
    for (int mt = 0; mt < 4; mt++) {
        #pragma unroll
        for (int half_ = 0; half_ < 2; half_++) {
            int row = row0 + wm + mt*16 + erow + half_*8;
            size_t rbase = (size_t)row * ldc;
            #pragma unroll
            for (int nt = 0; nt < 4; nt++) {
                int col = col0 + wn + nt*8 + ecol;
                float v0 = acc[mt][nt][half_*2+0];
                float v1 = acc[mt][nt][half_*2+1];
                if (bias) { v0 += bias[col]; v1 += bias[col+1]; }
                if (act)  { v0 = gelu_f(v0); v1 = gelu_f(v1); }
                if (add)  {
                    const float2 a2 = *(const float2*)&add[rbase + col];
                    v0 += a2.x; v1 += a2.y;
                }
                if (splitOut) {
                    *(__half2*)&Cah[rbase + col] =
                        __halves2half2(__float2half_rn(v0), __float2half_rn(v1));
                } else {
                    *(float2*)&C[rbase + col] = make_float2(v0, v1);
                }
            }
        }
    }
}

// ---------------- Per-segment partial memory contributions (tensor-core) ----------------
// grid (NSEG, BB*HH, NCH), 256 threads. S_p = sk^T[dk,pos] @ V[pos,dv], 128x128x128.
#define SKV_SKH 0
#define SKV_VH  32768
#define SKV_Z   65536
#define SKV_SMEM (65536 + 512)
__global__ __launch_bounds__(256, 1) void segkv_kernel(
    const __half* __restrict__ k, const __half* __restrict__ v,
    float* __restrict__ msp, float* __restrict__ zsp)
{
    extern __shared__ char sm[];
    const uint32_t base_a = smem_u32(sm);
    float* zacc = (float*)(sm + SKV_Z);
    const int seg = blockIdx.x, bh = blockIdx.y, ch = blockIdx.z;
    const int b = bh >> 3, h = bh & 7;
    const int tid = threadIdx.x;
    const int lane = tid & 31, wid = tid >> 5;
    const int wm = (wid >> 1) * 32;     // dk group
    const int wn = (wid & 1) * 64;      // dv group

    size_t gbase = ((size_t)b*SS + seg*SEG_ + ch*128)*QS + h*DK_;
    // load + convert k -> sk (fp16), load v; swizzled 256B-pitch rows
    #pragma unroll
    for (int ci = tid; ci < 2048; ci += 256) {    // 128 rows x 16 chunks(8 halves)
        int row = ci >> 4, c16 = ci & 15;
        uint4 ku = *(const uint4*)&k[gbase + (size_t)row*QS + c16*8];
        __half2* hp = (__half2*)&ku;
        #pragma unroll
        for (int t = 0; t < 4; t++) {
            float2 f = __half22float2(hp[t]);
            f.x = f.x > 0.f ? f.x + 1.f : __expf(f.x);
            f.y = f.y > 0.f ? f.y + 1.f : __expf(f.y);
            hp[t] = __halves2half2(__float2half_rn(f.x), __float2half_rn(f.y));
        }
        *(uint4*)&sm[SKV_SKH + SWZ(ci*16)] = ku;
        *(uint4*)&sm[SKV_VH + SWZ(ci*16)] = *(const uint4*)&v[gbase + (size_t)row*QS + c16*8];
    }
    __syncthreads();

    // z: column sums of sk
    if (tid < 128) {
        float za = 0.f;
        for (int pos = 0; pos < 128; pos++)
            za += __half2float(*(const __half*)&sm[SKV_SKH + swz256(pos, tid)]);
        zacc[tid] = za;
    }

    // mma: D[dk][dv] = sum_pos sk[pos][dk] * v[pos][dv]
    float acc[2][8][4];
    #pragma unroll
    for (int i=0;i<2;i++)
        #pragma unroll
        for (int j=0;j<8;j++)
            #pragma unroll
            for (int c=0;c<4;c++) acc[i][j][c]=0.f;

    #pragma unroll
    for (int kk = 0; kk < 8; kk++) {
        int krow = kk*16 + (lane & 15);
        uint32_t af[2][4];
        #pragma unroll
        for (int mt = 0; mt < 2; mt++) {
            uint32_t r0,r1,r2,r3;
            LDSM4T(r0,r1,r2,r3,
                   base_a + SKV_SKH + swz256(krow, wm + mt*16 + ((lane>>4)&1)*8));
            af[mt][0]=r0; af[mt][1]=r2; af[mt][2]=r1; af[mt][3]=r3;  // A-trans reorder
        }
        uint32_t bf[8][2];
        #pragma unroll
        for (int ntp = 0; ntp < 4; ntp++) {
            uint32_t r0,r1,r2,r3;
            LDSM4T(r0,r1,r2,r3,
                   base_a + SKV_VH + swz256(krow, wn + ntp*16 + ((lane>>4)&1)*8));
            bf[ntp*2][0]=r0; bf[ntp*2][1]=r1; bf[ntp*2+1][0]=r2; bf[ntp*2+1][1]=r3;
        }
        #pragma unroll
        for (int mt = 0; mt < 2; mt++)
            #pragma unroll
            for (int nt = 0; nt < 8; nt++)
                MMA16816(acc[mt][nt], af[mt], bf[nt]);
    }
    __syncthreads();

    const int slice = seg*NCH + ch;
    size_t obase = ((size_t)slice*32 + bh)*DK_*DK_;
    #pragma unroll
    for (int mt = 0; mt < 2; mt++) {
        #pragma unroll
        for (int hh = 0; hh < 2; hh++) {
            int row = wm + mt*16 + (lane>>2) + hh*8;
            #pragma unroll
            for (int nt = 0; nt < 8; nt++) {
                int col = wn + nt*8 + (lane&3)*2;
                *(float2*)&msp[obase + (size_t)row*DK_ + col] =
                    make_float2(acc[mt][nt][hh*2], acc[mt][nt][hh*2+1]);
            }
        }
    }
    if (tid < 128) zsp[((size_t)slice*32 + bh)*DK_ + tid] = zacc[tid];
}

// ---------------- Exclusive prefix over 8 segments -> fp16 M, fp32 z ----------------
__global__ void prefix_kernel(const float* __restrict__ msp, const float* __restrict__ zsp,
                              __half* __restrict__ mph, float* __restrict__ zp)
{
    size_t idx = (size_t)blockIdx.x*256 + threadIdx.x;
    const size_t stride = (size_t)BB*HH*DK_*DK_;
    if (idx < stride) {
        float a = 0.f;
        #pragma unroll
        for (int t = 0; t < NSEG; t++) {
            mph[t*stride + idx] = __float2half_rn(a);
            #pragma unroll
            for (int c = 0; c < NCH; c++)
                a += msp[(size_t)(t*NCH + c)*stride + idx];
        }
    }
    if (idx < (size_t)BB*HH*DK_) {
        const size_t zstr = (size_t)BB*HH*DK_;
        float a = 1.f/128.f;
        #pragma unroll
        for (int t = 0; t < NSEG; t++) {
            zp[t*zstr + idx] = a;
            #pragma unroll
            for (int c = 0; c < NCH; c++)
                a += zsp[(size_t)(t*NCH + c)*zstr + idx];
        }
    }
}

// 8 halves (uint4) -> two float4
__device__ __forceinline__ void h8_to_f8(uint4 u, float4& lo, float4& hi) {
    __half2* h = (__half2*)&u;
    float2 f0 = __half22float2(h[0]);
    float2 f1 = __half22float2(h[1]);
    float2 f2 = __half22float2(h[2]);
    float2 f3 = __half22float2(h[3]);
    lo = make_float4(f0.x, f0.y, f1.x, f1.y);
    hi = make_float4(f2.x, f2.y, f3.x, f3.y);
}

// ---------------- Tensor-core attention (FA2-style) ----------------
#define SM_QH   0
#define SM_KH   16384
#define SM_VH   32768
#define SM_PH   49152
#define SM_SQH  49152
#define SM_MH   16384
#define SM_SF   57344
#define SM_ST   74752
#define ATTN_SMEM (SM_ST + 1536)

__global__ __launch_bounds__(256, 1) void attn_kernel(
    const __half* __restrict__ q, const __half* __restrict__ k,
    const __half* __restrict__ v, const __half* __restrict__ mph,
    const float* __restrict__ zp, const float* __restrict__ betas,
    __half* __restrict__ Oah)
{
    extern __shared__ char sm[];
    const uint32_t base = smem_u32(sm);
    float* Sf   = (float*)(sm + SM_SF);       // [64][68]
    float* Zs   = (float*)(sm + SM_ST);       // 128
    float* mrow = Zs + 128;
    float* lrow = mrow + 64;
    float* arow = lrow + 64;
    float* drow = arow + 64;

    const int qt = blockIdx.x, seg = blockIdx.y;
    const int b = blockIdx.z >> 3, h = blockIdx.z & 7;
    const int tid = threadIdx.x;
    const int lane = tid & 31, wid = tid >> 5;
    const int wmS = (wid >> 2) * 32, wnS = (wid & 3) * 16;
    const int wmP = (wid >> 2) * 32, wnP = (wid & 3) * 32;

    const float* Z = zp + (((size_t)seg*BB + b)*HH + h)*DK_;
    size_t qbase = ((size_t)b*SS + seg*SEG_ + qt*64)*QS + h*DK_;
    #pragma unroll
    for (int ch = tid; ch < 1024; ch += 256) {
        int row = ch >> 4, c16 = ch & 15;
        *(uint4*)&sm[SM_QH + SWZ(ch*16)] = *(const uint4*)&q[qbase + (size_t)row*QS + c16*8];
    }
    if (tid < 128) Zs[tid] = Z[tid];
    if (tid < 64) { mrow[tid] = -INFINITY; lrow[tid] = 0.f; }

    float acc_o[2][4][4];
    #pragma unroll
    for (int i=0;i<2;i++)
        #pragma unroll
        for (int j=0;j<4;j++)
            #pragma unroll
            for (int c=0;c<4;c++) acc_o[i][j][c]=0.f;

    const float scale = 0.08838834764831845f;
    for (int kt = 0; kt <= qt; kt++) {
        __syncthreads();
        size_t kbase = ((size_t)b*SS + seg*SEG_ + kt*64)*QS + h*DK_;
        #pragma unroll
        for (int ch = tid; ch < 1024; ch += 256) {
            int row = ch >> 4, c16 = ch & 15;
            *(uint4*)&sm[SM_KH + SWZ(ch*16)] = *(const uint4*)&k[kbase + (size_t)row*QS + c16*8];
            *(uint4*)&sm[SM_VH + SWZ(ch*16)] = *(const uint4*)&v[kbase + (size_t)row*QS + c16*8];
        }
        __syncthreads();

        float accs[2][2][4];
        #pragma unroll
        for (int i=0;i<2;i++)
            #pragma unroll
            for (int j=0;j<2;j++)
                #pragma unroll
                for (int c=0;c<4;c++) accs[i][j][c]=0.f;
        #pragma unroll
        for (int kk = 0; kk < 8; kk++) {
            int eA = kk*16 + ((lane>>4)&1)*8;
            uint32_t af[2][4];
            #pragma unroll
            for (int mt = 0; mt < 2; mt++)
                LDSM4(af[mt][0],af[mt][1],af[mt][2],af[mt][3],
                      base + SM_QH + swz256(wmS + mt*16 + (lane&15), eA));
            int eB = kk*16 + ((lane>>3)&1)*8;
            uint32_t b0,b1,b2,b3;
            LDSM4(b0,b1,b2,b3,
                  base + SM_KH + swz256(wnS + (lane&7) + ((lane>>4)&1)*8, eB));
            uint32_t bf[2][2] = {{b0,b1},{b2,b3}};
            #pragma unroll
            for (int mt = 0; mt < 2; mt++)
                #pragma unroll
                for (int nt = 0; nt < 2; nt++)
                    MMA16816(accs[mt][nt], af[mt], bf[nt]);
        }
        #pragma unroll
        for (int mt = 0; mt < 2; mt++)
            #pragma unroll
            for (int nt = 0; nt < 2; nt++)
                #pragma unroll
                for (int c = 0; c < 4; c++) {
                    int r = wmS + mt*16 + (lane>>2) + ((c>>1)&1)*8;
                    int cc = wnS + nt*8 + (lane&3)*2 + (c&1);
                    float vv = accs[mt][nt][c]*scale;
                    if (kt == qt && cc > r) vv = -INFINITY;
                    Sf[r*68 + cc] = vv;
                }
        __syncthreads();

        {
            int r = tid >> 2, qd = tid & 3;
            float v16[16];
            float mx = -INFINITY;
            #pragma unroll
            for (int i = 0; i < 16; i++) {
                v16[i] = Sf[r*68 + qd*16 + i];
                mx = fmaxf(mx, v16[i]);
            }
            mx = fmaxf(mx, __shfl_xor_sync(0xffffffffu, mx, 1));
            mx = fmaxf(mx, __shfl_xor_sync(0xffffffffu, mx, 2));
            float mold = mrow[r];
            float mnew = fmaxf(mold, mx);
            float al = __expf(mold - mnew);
            float ps = 0.f;
            #pragma unroll
            for (int i = 0; i < 16; i += 2) {
                float p0 = __expf(v16[i]   - mnew);
                float p1 = __expf(v16[i+1] - mnew);
                ps += p0 + p1;
                *(__half2*)&sm[SM_PH + SWZ((uint32_t)(r*128 + (qd*16+i)*2))] =
                    __halves2half2(__float2half_rn(p0), __float2half_rn(p1));
            }
            ps += __shfl_xor_sync(0xffffffffu, ps, 1);
            ps += __shfl_xor_sync(0xffffffffu, ps, 2);
            if (qd == 0) {
                lrow[r] = lrow[r]*al + ps;
                mrow[r] = mnew;
                arow[r] = al;
            }
        }
        __syncthreads();

        float alv[2][2];
        #pragma unroll
        for (int mt = 0; mt < 2; mt++)
            #pragma unroll
            for (int hh = 0; hh < 2; hh++)
                alv[mt][hh] = arow[wmP + mt*16 + (lane>>2) + hh*8];
        #pragma unroll
        for (int mt = 0; mt < 2; mt++)
            #pragma unroll
            for (int nt = 0; nt < 4; nt++)
                #pragma unroll
                for (int c = 0; c < 4; c++)
                    acc_o[mt][nt][c] *= alv[mt][(c>>1)&1];
        #pragma unroll
        for (int kk2 = 0; kk2 < 4; kk2++) {
            int eA = kk2*16 + ((lane>>4)&1)*8;
            uint32_t af[2][4];
            #pragma unroll
            for (int mt = 0; mt < 2; mt++)
                LDSM4(af[mt][0],af[mt][1],af[mt][2],af[mt][3],
                      base + SM_PH + swz128(wmP + mt*16 + (lane&15), eA));
            uint32_t bf[4][2];
            #pragma unroll
            for (int ntp = 0; ntp < 2; ntp++) {
                int krow = kk2*16 + (lane&15);
                int n = wnP + ntp*16 + ((lane>>4)&1)*8;
                uint32_t r0,r1,r2,r3;
                LDSM4T(r0,r1,r2,r3, base + SM_VH + swz256(krow, n));
                bf[ntp*2][0]=r0; bf[ntp*2][1]=r1; bf[ntp*2+1][0]=r2; bf[ntp*2+1][1]=r3;
            }
            #pragma unroll
            for (int mt = 0; mt < 2; mt++)
                #pragma unroll
                for (int nt = 0; nt < 4; nt++)
                    MMA16816(acc_o[mt][nt], af[mt], bf[nt]);
        }
    }
    __syncthreads();

    #pragma unroll
    for (int ch = tid; ch < 1024; ch += 256) {
        uint4 u = *(const uint4*)&sm[SM_QH + SWZ(ch*16)];
        __half2* hp = (__half2*)&u;
        #pragma unroll
        for (int t = 0; t < 4; t++) {
            float2 f = __half22float2(hp[t]);
            f.x = f.x > 0.f ? f.x + 1.f : __expf(f.x);
            f.y = f.y > 0.f ? f.y + 1.f : __expf(f.y);
            hp[t] = __halves2half2(__float2half_rn(f.x), __float2half_rn(f.y));
        }
        *(uint4*)&sm[SM_SQH + SWZ(ch*16)] = u;
    }
    const __half* M = mph + (((size_t)seg*BB + b)*HH + h)*DK_*DK_;
    #pragma unroll
    for (int ch = tid; ch < 2048; ch += 256)
        *(uint4*)&sm[SM_MH + SWZ(ch*16)] = *(const uint4*)&M[(size_t)ch*8];
    __syncthreads();

    {
        int r = tid >> 2, qd = tid & 3;
        float ds = 0.f;
        #pragma unroll
        for (int j = 0; j < 4; j++) {
            int e = qd*32 + j*8;
            uint4 u = *(const uint4*)&sm[SM_SQH + swz256(r, e)];
            float4 lo, hi;
            h8_to_f8(u, lo, hi);
            const float4 z0 = *(const float4*)&Zs[e];
            const float4 z1 = *(const float4*)&Zs[e+4];
            ds += lo.x*z0.x + lo.y*z0.y + lo.z*z0.z + lo.w*z0.w
                + hi.x*z1.x + hi.y*z1.y + hi.z*z1.z + hi.w*z1.w;
        }
        ds += __shfl_xor_sync(0xffffffffu, ds, 1);
        ds += __shfl_xor_sync(0xffffffffu, ds, 2);
        if (qd == 0) drow[r] = ds;
    }
    __syncthreads();

    float acc_m[2][4][4];
    #pragma unroll
    for (int i=0;i<2;i++)
        #pragma unroll
        for (int j=0;j<4;j++)
            #pragma unroll
            for (int c=0;c<4;c++) acc_m[i][j][c]=0.f;
    #pragma unroll
    for (int kk = 0; kk < 8; kk++) {
        int eA = kk*16 + ((lane>>4)&1)*8;
        uint32_t af[2][4];
        #pragma unroll
        for (int mt = 0; mt < 2; mt++)
            LDSM4(af[mt][0],af[mt][1],af[mt][2],af[mt][3],
                  base + SM_SQH + swz256(wmP + mt*16 + (lane&15), eA));
        uint32_t bf[4][2];
        #pragma unroll
        for (int ntp = 0; ntp < 2; ntp++) {
            int d = kk*16 + (lane&15);
            int n = wnP + ntp*16 + ((lane>>4)&1)*8;
            uint32_t r0,r1,r2,r3;
            LDSM4T(r0,r1,r2,r3, base + SM_MH + swz256(d, n));
            bf[ntp*2][0]=r0; bf[ntp*2][1]=r1; bf[ntp*2+1][0]=r2; bf[ntp*2+1][1]=r3;
        }
        #pragma unroll
        for (int mt = 0; mt < 2; mt++)
            #pragma unroll
            for (int nt = 0; nt < 4; nt++)
                MMA16816(acc_m[mt][nt], af[mt], bf[nt]);
    }

    #pragma unroll
    for (int mt = 0; mt < 2; mt++) {
        #pragma unroll
        for (int hh = 0; hh < 2; hh++) {
            int row = wmP + mt*16 + (lane>>2) + hh*8;
            float dinv = 1.f / drow[row];
            float linv = 1.f / lrow[row];
            size_t ob = ((size_t)b*SS + seg*SEG_ + qt*64 + row)*DD + h*DK_;
            #pragma unroll
            for (int nt = 0; nt < 4; nt++) {
                int col = wnP + nt*8 + (lane&3)*2;
                float g0 = 1.f / (1.f + __expf(-betas[h*DK_ + col]));
                float g1 = 1.f / (1.f + __expf(-betas[h*DK_ + col + 1]));
                float u0 = g0*(acc_m[mt][nt][hh*2]  *dinv) + (1.f-g0)*(acc_o[mt][nt][hh*2]  *linv);
                float u1 = g1*(acc_m[mt][nt][hh*2+1]*dinv) + (1.f-g1)*(acc_o[mt][nt][hh*2+1]*linv);
                *(__half2*)&Oah[ob + col] = __halves2half2(__float2half_rn(u0), __float2half_rn(u1));
            }
        }
    }
}

// ---------------- launch ----------------
extern "C" void kernel_launch(void* const* d_in, const int* in_sizes, int n_in,
                              void* d_out, int out_size)
{
    const float* x     = (const float*)d_in[0];
    const float* ln_g  = (const float*)d_in[1];
    const float* ln_b  = (const float*)d_in[2];
    const float* Wq    = (const float*)d_in[3];
    const float* Wk    = (const float*)d_in[4];
    const float* Wv    = (const float*)d_in[5];
    const float* Wo    = (const float*)d_in[6];
    const float* betas = (const float*)d_in[7];
    const float* w1    = (const float*)d_in[8];
    const float* b1    = (const float*)d_in[9];
    const float* w2    = (const float*)d_in[10];
    const float* b2    = (const float*)d_in[11];
    float* out = (float*)d_out;

    float *x1, *ff, *msp, *zsp, *zp;
    __half *qkvh, *mph, *ah, *bqkv, *bo, *bw1, *bw2;
    cudaGetSymbolAddress((void**)&qkvh, g_qkvh);
    cudaGetSymbolAddress((void**)&x1, g_x1);
    cudaGetSymbolAddress((void**)&ff, g_ff);
    cudaGetSymbolAddress((void**)&msp, g_msp);
    cudaGetSymbolAddress((void**)&mph, g_mph);
    cudaGetSymbolAddress((void**)&zsp, g_zsp);
    cudaGetSymbolAddress((void**)&zp, g_zp);
    cudaGetSymbolAddress((void**)&ah, g_ah);
    cudaGetSymbolAddress((void**)&bqkv, g_bqkv);
    cudaGetSymbolAddress((void**)&bo, g_bo);
    cudaGetSymbolAddress((void**)&bw1, g_bw1);
    cudaGetSymbolAddress((void**)&bw2, g_bw2);

    __half* ah2 = (__half*)ff;     // FFN1 hi-only output

    cudaFuncSetAttribute(attn_kernel, cudaFuncAttributeMaxDynamicSharedMemorySize, ATTN_SMEM);
    cudaFuncSetAttribute(hgemm_kernel, cudaFuncAttributeMaxDynamicSharedMemorySize, HG_SMEM);
    cudaFuncSetAttribute(segkv_kernel, cudaFuncAttributeMaxDynamicSharedMemorySize, SKV_SMEM);

    dim3 wblk(32, 8);

    // weight prep
    prep_w_kernel<<<dim3(1024/32, 1024/32), wblk>>>(Wq, bqkv,                      1024, 1024);
    prep_w_kernel<<<dim3(1024/32, 1024/32), wblk>>>(Wk, bqkv + (size_t)1024*1024,  1024, 1024);
    prep_w_kernel<<<dim3(1024/32, 1024/32), wblk>>>(Wv, bqkv + (size_t)2048*1024,  1024, 1024);
    prep_w_kernel<<<dim3(1024/32, 1024/32), wblk>>>(Wo, bo, 1024, 1024);
    prep_w_kernel<<<dim3(4096/32, 1024/32), wblk>>>(w1, bw1, 1024, 4096);
    prep_w_kernel<<<dim3(1024/32, 4096/32), wblk>>>(w2, bw2, 4096, 1024);

    // 1) LN1 -> fp16
    ln_kernel<<<MROWS, 256>>>(x, ln_g, ln_b, ah);
    // 2) fused QKV projection -> fp16 qkv
    hgemm_kernel<<<dim3(QS/128, MROWS/128), 256, HG_SMEM>>>(ah, bqkv, nullptr, nullptr,
                                                            nullptr, qkvh, MROWS, QS, QS, DD, 0, 2);
    // 3-5) infini-attention
    segkv_kernel<<<dim3(NSEG, BB*HH, NCH), 256, SKV_SMEM>>>(qkvh + 1024, qkvh + 2048, msp, zsp);
    prefix_kernel<<<(BB*HH*DK_*DK_)/256, 256>>>(msp, zsp, mph, zp);
    attn_kernel<<<dim3(8, NSEG, BB*HH), 256, ATTN_SMEM>>>(qkvh, qkvh + 1024, qkvh + 2048,
                                                          mph, zp, betas, ah);
    // 6) output projection + residual
    dim3 g1(DD/128, MROWS/128);
    hgemm_kernel<<<g1, 256, HG_SMEM>>>(ah, bo, nullptr, x, x1, nullptr,
                                       MROWS, DD, DD, DD, 0, 0);
    // 7) LN2 -> fp16
    ln_kernel<<<MROWS, 256>>>(x1, ln_g, ln_b, ah);
    // 8) FFN1 + bias + gelu -> fp16
    hgemm_kernel<<<dim3(DH_/128, MROWS/128), 256, HG_SMEM>>>(ah, bw1, b1, nullptr, nullptr,
                                                             ah2, MROWS, DH_, DH_, DD, 1, 2);
    // 9) FFN2 + bias + residual -> out
    hgemm_kernel<<<dim3(DD/128, MROWS/128), 256, HG_SMEM>>>(ah2, bw2, b2, x1, out,
                                                            nullptr, MROWS, DD, DD, DH_, 0, 0);
}

// round 15
// speedup vs baseline: 1.7553x; 1.0283x over previous
#include <cuda_runtime.h>
#include <cuda_fp16.h>
#include <math.h>
#include <stdint.h>

// Problem constants
#define BB   4
#define SS   4096
#define DD   1024
#define HH   8
#define DK_  128
#define SEG_ 512
#define NSEG 8
#define DH_  4096
#define MROWS (BB*SS)   // 16384
#define QS   3072       // fused qkv row stride
#define NCH  4          // segkv position chunks per segment

// ---------------- scratch ----------------
__device__ __half g_qkvh[(size_t)MROWS*QS];            // fp16 q|k|v
__device__ float g_x1[(size_t)MROWS*DD];
__device__ float g_ff[(size_t)MROWS*DH_];              // reused: FFN1 hi fp16 output
__device__ float g_msp[(size_t)NSEG*NCH*BB*HH*DK_*DK_]; // partial seg outer products
__device__ __half g_mph[(size_t)NSEG*BB*HH*DK_*DK_];    // fp16 prefix memory
__device__ float g_zsp[(size_t)NSEG*NCH*BB*HH*DK_];
__device__ float g_zp [(size_t)NSEG*BB*HH*DK_];
// fp16 activation buffer [M][1024] (hi only)
__device__ __half g_ah[(size_t)MROWS*DD];
// transposed fp16 weights [N][K]
__device__ __half g_bqkv[(size_t)QS*DD];
__device__ __half g_bo[(size_t)DD*DD];
__device__ __half g_bw1[(size_t)DH_*DD];
__device__ __half g_bw2[(size_t)DD*DH_];

__device__ __forceinline__ float gelu_f(float x) {
    float x3 = x*x*x;
    float t = tanhf(0.7978845608028654f*(x + 0.044715f*x3));
    return 0.5f*x*(1.f + t);
}

// ================= PTX helpers =================
__device__ __forceinline__ uint32_t smem_u32(const void* p) {
    uint32_t a;
    asm("{ .reg .u64 t; cvta.to.shared.u64 t, %1; cvt.u32.u64 %0, t; }" : "=r"(a) : "l"(p));
    return a;
}
__device__ __forceinline__ void cpa16(uint32_t d, const void* s) {
    asm volatile("cp.async.cg.shared.global [%0], [%1], 16;"
                 :: "r"(d), "l"(__cvta_generic_to_global((void*)s)) : "memory");
}
#define SWZ(x) ((x) ^ (((x) >> 3) & 0x70))

#define LDSM4(r0,r1,r2,r3,addr) \
    asm volatile("ldmatrix.sync.aligned.m8n8.x4.shared.b16 {%0,%1,%2,%3}, [%4];" \
                 : "=r"(r0),"=r"(r1),"=r"(r2),"=r"(r3) : "r"(addr))

#define LDSM4T(r0,r1,r2,r3,addr) \
    asm volatile("ldmatrix.sync.aligned.m8n8.x4.trans.shared.b16 {%0,%1,%2,%3}, [%4];" \
                 : "=r"(r0),"=r"(r1),"=r"(r2),"=r"(r3) : "r"(addr))

#define MMA16816(d, a, b) \
    asm volatile("mma.sync.aligned.m16n8k16.row.col.f32.f16.f16.f32 " \
                 "{%0,%1,%2,%3}, {%4,%5,%6,%7}, {%8,%9}, {%0,%1,%2,%3};" \
                 : "+f"((d)[0]),"+f"((d)[1]),"+f"((d)[2]),"+f"((d)[3]) \
                 : "r"((a)[0]),"r"((a)[1]),"r"((a)[2]),"r"((a)[3]), \
                   "r"((b)[0]),"r"((b)[1]))

// swizzled byte offsets: 256B-pitch rows (128 fp16) and 128B-pitch rows (64 fp16)
__device__ __forceinline__ uint32_t swz256(int row, int e) {
    return SWZ((uint32_t)((row*2 + (e>>6))*128 + (e&63)*2));
}
__device__ __forceinline__ uint32_t swz128(int row, int e) {
    return SWZ((uint32_t)(row*128 + e*2));
}

// ---------------- LayerNorm -> fp16 (hi only) ----------------
__global__ void ln_kernel(const float* __restrict__ x, const float* __restrict__ gamma,
                          const float* __restrict__ beta, __half* __restrict__ Ah) {
    __shared__ float s1[256], s2[256];
    const int row = blockIdx.x;
    const int tid = threadIdx.x;
    const float* xr = x + (size_t)row*DD;
    float4 v = *(const float4*)&xr[tid*4];
    float s  = v.x+v.y+v.z+v.w;
    float ss = v.x*v.x+v.y*v.y+v.z*v.z+v.w*v.w;
    s1[tid]=s; s2[tid]=ss; __syncthreads();
    for (int o=128;o>0;o>>=1){ if(tid<o){s1[tid]+=s1[tid+o]; s2[tid]+=s2[tid+o];} __syncthreads(); }
    float mu  = s1[0]*(1.f/DD);
    float var = s2[0]*(1.f/DD) - mu*mu;
    float inv = rsqrtf(var + 1e-5f);
    float4 g  = *(const float4*)&gamma[tid*4];
    float4 bt = *(const float4*)&beta[tid*4];
    float o0 = (v.x-mu)*inv*g.x + bt.x;
    float o1 = (v.y-mu)*inv*g.y + bt.y;
    float o2 = (v.z-mu)*inv*g.z + bt.z;
    float o3 = (v.w-mu)*inv*g.w + bt.w;
    size_t base = (size_t)row*DD + tid*4;
    *(__half2*)&Ah[base]   = __halves2half2(__float2half_rn(o0), __float2half_rn(o1));
    *(__half2*)&Ah[base+2] = __halves2half2(__float2half_rn(o2), __float2half_rn(o3));
}

// ---------------- Weight prep ----------------
__global__ void prep_w_kernel(const float* __restrict__ W, __half* __restrict__ Bp,
                              int K, int N) {
    __shared__ float ts[32][33];
    const int n0 = blockIdx.x*32, k0 = blockIdx.y*32;
    const int tx = threadIdx.x, ty = threadIdx.y;   // (32,8)
    #pragma unroll
    for (int i = 0; i < 4; i++)
        ts[ty+8*i][tx] = W[(size_t)(k0+ty+8*i)*N + n0+tx];
    __syncthreads();
    #pragma unroll
    for (int i = 0; i < 4; i++) {
        int nl = ty + 8*i;
        Bp[(size_t)(n0+nl)*K + k0+tx] = __float2half_rn(ts[tx][nl]);
    }
}

// ---------------- mma.sync fp16 GEMM ----------------
#define GBK 64
#define NSTG 3
#define STB 16384
#define STAGE_BYTES (2*STB)
#define HG_SMEM (NSTG*STAGE_BYTES)

__global__ __launch_bounds__(256, 2) void hgemm_kernel(
    const __half* __restrict__ Ah, const __half* __restrict__ Bp,
    const float* __restrict__ bias, const float* __restrict__ add,
    float* __restrict__ C, __half* __restrict__ Cah,
    int M, int N, int ldc, int K, int act, int splitOut)
{
    extern __shared__ char dsm[];
    const uint32_t sb = smem_u32(dsm);
    const int tid = threadIdx.x;
    const int lane = tid & 31, wid = tid >> 5;
    const int row0 = blockIdx.y * 128, col0 = blockIdx.x * 128;
    const int NT = K / GBK;

    const int wm = (wid >> 2) * 64;
    const int wn = (wid & 3) * 32;

    float acc[4][4][4];
    #pragma unroll
    for (int i=0;i<4;i++)
        #pragma unroll
        for (int j=0;j<4;j++)
            #pragma unroll
            for (int c=0;c<4;c++) acc[i][j][c]=0.f;

    auto load_tile = [&](int t, int s) {
        int k0 = t * GBK;
        uint32_t stA = sb + s*STAGE_BYTES;
        uint32_t stB = stA + STB;
        #pragma unroll
        for (int i = 0; i < 4; i++) {
            int ch = i*256 + tid;
            int r = ch >> 3, c = (ch & 7) * 8;
            cpa16(stA + SWZ(ch*16), Ah + (size_t)(row0 + r)*K + k0 + c);
            cpa16(stB + SWZ(ch*16), Bp + (size_t)(col0 + r)*K + k0 + c);
        }
        asm volatile("cp.async.commit_group;" ::: "memory");
    };

    load_tile(0, 0);
    if (NT > 1) load_tile(1, 1);

    const int aRow = wm + (lane & 15);
    const int aColB = ((lane >> 4) & 1) * 16;
    const int bRow = wn + (lane & 7) + ((lane >> 4) & 1) * 8;
    const int bColB = ((lane >> 3) & 1) * 16;

    for (int t = 0; t < NT; t++) {
        if (t < NT-1) asm volatile("cp.async.wait_group 1;" ::: "memory");
        else          asm volatile("cp.async.wait_group 0;" ::: "memory");
        __syncthreads();
        if (t + 2 < NT) load_tile(t + 2, (t + 2) % NSTG);
        uint32_t stA = sb + (t % NSTG)*STAGE_BYTES;
        uint32_t stB = stA + STB;
        #pragma unroll
        for (int kk = 0; kk < 4; kk++) {
            uint32_t af[4][4];
            #pragma unroll
            for (int mt = 0; mt < 4; mt++) {
                uint32_t addr = stA + SWZ((uint32_t)(aRow + mt*16)*128 + kk*32 + aColB);
                LDSM4(af[mt][0], af[mt][1], af[mt][2], af[mt][3], addr);
            }
            uint32_t bf[4][2];
            #pragma unroll
            for (int nt2 = 0; nt2 < 2; nt2++) {
                uint32_t r0,r1,r2,r3;
                uint32_t addr = stB + SWZ((uint32_t)(bRow + nt2*16)*128 + kk*32 + bColB);
                LDSM4(r0, r1, r2, r3, addr);
                bf[nt2*2][0]=r0; bf[nt2*2][1]=r1; bf[nt2*2+1][0]=r2; bf[nt2*2+1][1]=r3;
            }
            #pragma unroll
            for (int mt = 0; mt < 4; mt++)
                #pragma unroll
                for (int nt = 0; nt < 4; nt++)
                    MMA16816(acc[mt][nt], af[mt], bf[nt]);
        }
        __syncthreads();
    }

    const int erow = lane >> 2, ecol = (lane & 3) * 2;
    #pragma unroll
    for (int mt = 0; mt < 4; mt++) {
        #pragma unroll
        for (int half_ = 0; half_ < 2; half_++) {
            int row = row0 + wm + mt*16 + erow + half_*8;
            size_t rbase = (size_t)row * ldc;
            #pragma unroll
            for (int nt = 0; nt < 4; nt++) {
                int col = col0 + wn + nt*8 + ecol;
                float v0 = acc[mt][nt][half_*2+0];
                float v1 = acc[mt][nt][half_*2+1];
                if (bias) { v0 += bias[col]; v1 += bias[col+1]; }
                if (act)  { v0 = gelu_f(v0); v1 = gelu_f(v1); }
                if (add)  {
                    const float2 a2 = *(const float2*)&add[rbase + col];
                    v0 += a2.x; v1 += a2.y;
                }
                if (splitOut) {
                    *(__half2*)&Cah[rbase + col] =
                        __halves2half2(__float2half_rn(v0), __float2half_rn(v1));
                } else {
                    *(float2*)&C[rbase + col] = make_float2(v0, v1);
                }
            }
        }
    }
}

// ---------------- Per-segment partial memory contributions (tensor-core) ----------------
#define SKV_SKH 0
#define SKV_VH  32768
#define SKV_Z   65536
#define SKV_SMEM (65536 + 512)
__global__ __launch_bounds__(256, 1) void segkv_kernel(
    const __half* __restrict__ k, const __half* __restrict__ v,
    float* __restrict__ msp, float* __restrict__ zsp)
{
    extern __shared__ char sm[];
    const uint32_t base_a = smem_u32(sm);
    float* zacc = (float*)(sm + SKV_Z);
    const int seg = blockIdx.x, bh = blockIdx.y, ch = blockIdx.z;
    const int b = bh >> 3, h = bh & 7;
    const int tid = threadIdx.x;
    const int lane = tid & 31, wid = tid >> 5;
    const int wm = (wid >> 1) * 32;
    const int wn = (wid & 1) * 64;

    size_t gbase = ((size_t)b*SS + seg*SEG_ + ch*128)*QS + h*DK_;
    #pragma unroll
    for (int ci = tid; ci < 2048; ci += 256) {
        int row = ci >> 4, c16 = ci & 15;
        uint4 ku = *(const uint4*)&k[gbase + (size_t)row*QS + c16*8];
        __half2* hp = (__half2*)&ku;
        #pragma unroll
        for (int t = 0; t < 4; t++) {
            float2 f = __half22float2(hp[t]);
            f.x = f.x > 0.f ? f.x + 1.f : __expf(f.x);
            f.y = f.y > 0.f ? f.y + 1.f : __expf(f.y);
            hp[t] = __halves2half2(__float2half_rn(f.x), __float2half_rn(f.y));
        }
        *(uint4*)&sm[SKV_SKH + SWZ(ci*16)] = ku;
        *(uint4*)&sm[SKV_VH + SWZ(ci*16)] = *(const uint4*)&v[gbase + (size_t)row*QS + c16*8];
    }
    __syncthreads();

    if (tid < 128) {
        float za = 0.f;
        for (int pos = 0; pos < 128; pos++)
            za += __half2float(*(const __half*)&sm[SKV_SKH + swz256(pos, tid)]);
        zacc[tid] = za;
    }

    float acc[2][8][4];
    #pragma unroll
    for (int i=0;i<2;i++)
        #pragma unroll
        for (int j=0;j<8;j++)
            #pragma unroll
            for (int c=0;c<4;c++) acc[i][j][c]=0.f;

    #pragma unroll
    for (int kk = 0; kk < 8; kk++) {
        int krow = kk*16 + (lane & 15);
        uint32_t af[2][4];
        #pragma unroll
        for (int mt = 0; mt < 2; mt++) {
            uint32_t r0,r1,r2,r3;
            LDSM4T(r0,r1,r2,r3,
                   base_a + SKV_SKH + swz256(krow, wm + mt*16 + ((lane>>4)&1)*8));
            af[mt][0]=r0; af[mt][1]=r2; af[mt][2]=r1; af[mt][3]=r3;
        }
        uint32_t bf[8][2];
        #pragma unroll
        for (int ntp = 0; ntp < 4; ntp++) {
            uint32_t r0,r1,r2,r3;
            LDSM4T(r0,r1,r2,r3,
                   base_a + SKV_VH + swz256(krow, wn + ntp*16 + ((lane>>4)&1)*8));
            bf[ntp*2][0]=r0; bf[ntp*2][1]=r1; bf[ntp*2+1][0]=r2; bf[ntp*2+1][1]=r3;
        }
        #pragma unroll
        for (int mt = 0; mt < 2; mt++)
            #pragma unroll
            for (int nt = 0; nt < 8; nt++)
                MMA16816(acc[mt][nt], af[mt], bf[nt]);
    }
    __syncthreads();

    const int slice = seg*NCH + ch;
    size_t obase = ((size_t)slice*32 + bh)*DK_*DK_;
    #pragma unroll
    for (int mt = 0; mt < 2; mt++) {
        #pragma unroll
        for (int hh = 0; hh < 2; hh++) {
            int row = wm + mt*16 + (lane>>2) + hh*8;
            #pragma unroll
            for (int nt = 0; nt < 8; nt++) {
                int col = wn + nt*8 + (lane&3)*2;
                *(float2*)&msp[obase + (size_t)row*DK_ + col] =
                    make_float2(acc[mt][nt][hh*2], acc[mt][nt][hh*2+1]);
            }
        }
    }
    if (tid < 128) zsp[((size_t)slice*32 + bh)*DK_ + tid] = zacc[tid];
}

// ---------------- Exclusive prefix -> fp16 M, fp32 z ----------------
__global__ void prefix_kernel(const float* __restrict__ msp, const float* __restrict__ zsp,
                              __half* __restrict__ mph, float* __restrict__ zp)
{
    size_t idx = (size_t)blockIdx.x*256 + threadIdx.x;
    const size_t stride = (size_t)BB*HH*DK_*DK_;
    if (idx < stride) {
        float a = 0.f;
        #pragma unroll
        for (int t = 0; t < NSEG; t++) {
            mph[t*stride + idx] = __float2half_rn(a);
            #pragma unroll
            for (int c = 0; c < NCH; c++)
                a += msp[(size_t)(t*NCH + c)*stride + idx];
        }
    }
    if (idx < (size_t)BB*HH*DK_) {
        const size_t zstr = (size_t)BB*HH*DK_;
        float a = 1.f/128.f;
        #pragma unroll
        for (int t = 0; t < NSEG; t++) {
            zp[t*zstr + idx] = a;
            #pragma unroll
            for (int c = 0; c < NCH; c++)
                a += zsp[(size_t)(t*NCH + c)*zstr + idx];
        }
    }
}

// 8 halves (uint4) -> two float4
__device__ __forceinline__ void h8_to_f8(uint4 u, float4& lo, float4& hi) {
    __half2* h = (__half2*)&u;
    float2 f0 = __half22float2(h[0]);
    float2 f1 = __half22float2(h[1]);
    float2 f2 = __half22float2(h[2]);
    float2 f3 = __half22float2(h[3]);
    lo = make_float4(f0.x, f0.y, f1.x, f1.y);
    hi = make_float4(f2.x, f2.y, f3.x, f3.y);
}

// ---------------- Tensor-core attention (FA2-style, cp.async double-buffered K/V) ----------------
// smem: Qh 0..16K | stage0 K/V 16K..48K | stage1 K/V 48K..80K | Ph 80K..88K |
//       M reuses 16K..48K | sqh reuses 48K..64K | Sf 88K..105K | stats 105K..
#define SM_QH   0
#define SM_S0   16384
#define SM_S1   49152
#define SM_PH   81920
#define SM_MH   16384
#define SM_SQH  49152
#define SM_SF   90112
#define SM_ST   107520
#define ATTN_SMEM (SM_ST + 1536)

__global__ __launch_bounds__(256, 1) void attn_kernel(
    const __half* __restrict__ q, const __half* __restrict__ k,
    const __half* __restrict__ v, const __half* __restrict__ mph,
    const float* __restrict__ zp, const float* __restrict__ betas,
    __half* __restrict__ Oah)
{
    extern __shared__ char sm[];
    const uint32_t base = smem_u32(sm);
    float* Sf   = (float*)(sm + SM_SF);       // [64][68]
    float* Zs   = (float*)(sm + SM_ST);       // 128
    float* mrow = Zs + 128;
    float* lrow = mrow + 64;
    float* arow = lrow + 64;
    float* drow = arow + 64;

    const int qt = blockIdx.x, seg = blockIdx.y;
    const int b = blockIdx.z >> 3, h = blockIdx.z & 7;
    const int tid = threadIdx.x;
    const int lane = tid & 31, wid = tid >> 5;
    const int wmS = (wid >> 2) * 32, wnS = (wid & 3) * 16;
    const int wmP = (wid >> 2) * 32, wnP = (wid & 3) * 32;

    const float* Z = zp + (((size_t)seg*BB + b)*HH + h)*DK_;
    size_t qbase = ((size_t)b*SS + seg*SEG_ + qt*64)*QS + h*DK_;
    #pragma unroll
    for (int ch = tid; ch < 1024; ch += 256) {
        int row = ch >> 4, c16 = ch & 15;
        *(uint4*)&sm[SM_QH + SWZ(ch*16)] = *(const uint4*)&q[qbase + (size_t)row*QS + c16*8];
    }
    if (tid < 128) Zs[tid] = Z[tid];
    if (tid < 64) { mrow[tid] = -INFINITY; lrow[tid] = 0.f; }

    // K/V tile prefetch (cp.async) into stage st
    auto ldkv = [&](int kt, int st) {
        size_t kb = ((size_t)b*SS + seg*SEG_ + kt*64)*QS + h*DK_;
        uint32_t K_ = base + SM_S0 + (uint32_t)st*32768u;
        uint32_t V_ = K_ + 16384u;
        #pragma unroll
        for (int ch = tid; ch < 1024; ch += 256) {
            int row = ch >> 4, c16 = ch & 15;
            cpa16(K_ + SWZ(ch*16), &k[kb + (size_t)row*QS + c16*8]);
            cpa16(V_ + SWZ(ch*16), &v[kb + (size_t)row*QS + c16*8]);
        }
        asm volatile("cp.async.commit_group;" ::: "memory");
    };

    ldkv(0, 0);
    if (qt >= 1) ldkv(1, 1);

    float acc_o[2][4][4];
    #pragma unroll
    for (int i=0;i<2;i++)
        #pragma unroll
        for (int j=0;j<4;j++)
            #pragma unroll
            for (int c=0;c<4;c++) acc_o[i][j][c]=0.f;

    const float scale = 0.08838834764831845f;
    for (int kt = 0; kt <= qt; kt++) {
        const int s = kt & 1;
        const uint32_t KH = SM_S0 + (uint32_t)s*32768u;
        const uint32_t VH = KH + 16384u;
        if (kt < qt) asm volatile("cp.async.wait_group 1;" ::: "memory");
        else         asm volatile("cp.async.wait_group 0;" ::: "memory");
        __syncthreads();    // tile kt visible; prior-iteration reads of this stage done

        // S = Q K^T
        float accs[2][2][4];
        #pragma unroll
        for (int i=0;i<2;i++)
            #pragma unroll
            for (int j=0;j<2;j++)
                #pragma unroll
                for (int c=0;c<4;c++) accs[i][j][c]=0.f;
        #pragma unroll
        for (int kk = 0; kk < 8; kk++) {
            int eA = kk*16 + ((lane>>4)&1)*8;
            uint32_t af[2][4];
            #pragma unroll
            for (int mt = 0; mt < 2; mt++)
                LDSM4(af[mt][0],af[mt][1],af[mt][2],af[mt][3],
                      base + SM_QH + swz256(wmS + mt*16 + (lane&15), eA));
            int eB = kk*16 + ((lane>>3)&1)*8;
            uint32_t b0,b1,b2,b3;
            LDSM4(b0,b1,b2,b3,
                  base + KH + swz256(wnS + (lane&7) + ((lane>>4)&1)*8, eB));
            uint32_t bf[2][2] = {{b0,b1},{b2,b3}};
            #pragma unroll
            for (int mt = 0; mt < 2; mt++)
                #pragma unroll
                for (int nt = 0; nt < 2; nt++)
                    MMA16816(accs[mt][nt], af[mt], bf[nt]);
        }
        #pragma unroll
        for (int mt = 0; mt < 2; mt++)
            #pragma unroll
            for (int nt = 0; nt < 2; nt++)
                #pragma unroll
                for (int c = 0; c < 4; c++) {
                    int r = wmS + mt*16 + (lane>>2) + ((c>>1)&1)*8;
                    int cc = wnS + nt*8 + (lane&3)*2 + (c&1);
                    float vv = accs[mt][nt][c]*scale;
                    if (kt == qt && cc > r) vv = -INFINITY;
                    Sf[r*68 + cc] = vv;
                }
        __syncthreads();

        // softmax: 4 lanes per row
        {
            int r = tid >> 2, qd = tid & 3;
            float v16[16];
            float mx = -INFINITY;
            #pragma unroll
            for (int i = 0; i < 16; i++) {
                v16[i] = Sf[r*68 + qd*16 + i];
                mx = fmaxf(mx, v16[i]);
            }
            mx = fmaxf(mx, __shfl_xor_sync(0xffffffffu, mx, 1));
            mx = fmaxf(mx, __shfl_xor_sync(0xffffffffu, mx, 2));
            float mold = mrow[r];
            float mnew = fmaxf(mold, mx);
            float al = __expf(mold - mnew);
            float ps = 0.f;
            #pragma unroll
            for (int i = 0; i < 16; i += 2) {
                float p0 = __expf(v16[i]   - mnew);
                float p1 = __expf(v16[i+1] - mnew);
                ps += p0 + p1;
                *(__half2*)&sm[SM_PH + SWZ((uint32_t)(r*128 + (qd*16+i)*2))] =
                    __halves2half2(__float2half_rn(p0), __float2half_rn(p1));
            }
            ps += __shfl_xor_sync(0xffffffffu, ps, 1);
            ps += __shfl_xor_sync(0xffffffffu, ps, 2);
            if (qd == 0) {
                lrow[r] = lrow[r]*al + ps;
                mrow[r] = mnew;
                arow[r] = al;
            }
        }
        __syncthreads();

        // rescale + PV
        float alv[2][2];
        #pragma unroll
        for (int mt = 0; mt < 2; mt++)
            #pragma unroll
            for (int hh = 0; hh < 2; hh++)
                alv[mt][hh] = arow[wmP + mt*16 + (lane>>2) + hh*8];
        #pragma unroll
        for (int mt = 0; mt < 2; mt++)
            #pragma unroll
            for (int nt = 0; nt < 4; nt++)
                #pragma unroll
                for (int c = 0; c < 4; c++)
                    acc_o[mt][nt][c] *= alv[mt][(c>>1)&1];
        #pragma unroll
        for (int kk2 = 0; kk2 < 4; kk2++) {
            int eA = kk2*16 + ((lane>>4)&1)*8;
            uint32_t af[2][4];
            #pragma unroll
            for (int mt = 0; mt < 2; mt++)
                LDSM4(af[mt][0],af[mt][1],af[mt][2],af[mt][3],
                      base + SM_PH + swz128(wmP + mt*16 + (lane&15), eA));
            uint32_t bf[4][2];
            #pragma unroll
            for (int ntp = 0; ntp < 2; ntp++) {
                int krow = kk2*16 + (lane&15);
                int n = wnP + ntp*16 + ((lane>>4)&1)*8;
                uint32_t r0,r1,r2,r3;
                LDSM4T(r0,r1,r2,r3, base + VH + swz256(krow, n));
                bf[ntp*2][0]=r0; bf[ntp*2][1]=r1; bf[ntp*2+1][0]=r2; bf[ntp*2+1][1]=r3;
            }
            #pragma unroll
            for (int mt = 0; mt < 2; mt++)
                #pragma unroll
                for (int nt = 0; nt < 4; nt++)
                    MMA16816(acc_o[mt][nt], af[mt], bf[nt]);
        }
        __syncthreads();    // stage s fully consumed
        if (kt + 2 <= qt) ldkv(kt + 2, s);
    }

    // build sqh = elu(q)+1 (fp16) at SM_SQH ; load M (fp16) into SM_MH (32KB)
    #pragma unroll
    for (int ch = tid; ch < 1024; ch += 256) {
        uint4 u = *(const uint4*)&sm[SM_QH + SWZ(ch*16)];
        __half2* hp = (__half2*)&u;
        #pragma unroll
        for (int t = 0; t < 4; t++) {
            float2 f = __half22float2(hp[t]);
            f.x = f.x > 0.f ? f.x + 1.f : __expf(f.x);
            f.y = f.y > 0.f ? f.y + 1.f : __expf(f.y);
            hp[t] = __halves2half2(__float2half_rn(f.x), __float2half_rn(f.y));
        }
        *(uint4*)&sm[SM_SQH + SWZ(ch*16)] = u;
    }
    const __half* M = mph + (((size_t)seg*BB + b)*HH + h)*DK_*DK_;
    #pragma unroll
    for (int ch = tid; ch < 2048; ch += 256)
        *(uint4*)&sm[SM_MH + SWZ(ch*16)] = *(const uint4*)&M[(size_t)ch*8];
    __syncthreads();

    // ds = sq . Z
    {
        int r = tid >> 2, qd = tid & 3;
        float ds = 0.f;
        #pragma unroll
        for (int j = 0; j < 4; j++) {
            int e = qd*32 + j*8;
            uint4 u = *(const uint4*)&sm[SM_SQH + swz256(r, e)];
            float4 lo, hi;
            h8_to_f8(u, lo, hi);
            const float4 z0 = *(const float4*)&Zs[e];
            const float4 z1 = *(const float4*)&Zs[e+4];
            ds += lo.x*z0.x + lo.y*z0.y + lo.z*z0.z + lo.w*z0.w
                + hi.x*z1.x + hi.y*z1.y + hi.z*z1.z + hi.w*z1.w;
        }
        ds += __shfl_xor_sync(0xffffffffu, ds, 1);
        ds += __shfl_xor_sync(0xffffffffu, ds, 2);
        if (qd == 0) drow[r] = ds;
    }
    __syncthreads();

    // retrieval: am = sq @ M
    float acc_m[2][4][4];
    #pragma unroll
    for (int i=0;i<2;i++)
        #pragma unroll
        for (int j=0;j<4;j++)
            #pragma unroll
            for (int c=0;c<4;c++) acc_m[i][j][c]=0.f;
    #pragma unroll
    for (int kk = 0; kk < 8; kk++) {
        int eA = kk*16 + ((lane>>4)&1)*8;
        uint32_t af[2][4];
        #pragma unroll
        for (int mt = 0; mt < 2; mt++)
            LDSM4(af[mt][0],af[mt][1],af[mt][2],af[mt][3],
                  base + SM_SQH + swz256(wmP + mt*16 + (lane&15), eA));
        uint32_t bf[4][2];
        #pragma unroll
        for (int ntp = 0; ntp < 2; ntp++) {
            int d = kk*16 + (lane&15);
            int n = wnP + ntp*16 + ((lane>>4)&1)*8;
            uint32_t r0,r1,r2,r3;
            LDSM4T(r0,r1,r2,r3, base + SM_MH + swz256(d, n));
            bf[ntp*2][0]=r0; bf[ntp*2][1]=r1; bf[ntp*2+1][0]=r2; bf[ntp*2+1][1]=r3;
        }
        #pragma unroll
        for (int mt = 0; mt < 2; mt++)
            #pragma unroll
            for (int nt = 0; nt < 4; nt++)
                MMA16816(acc_m[mt][nt], af[mt], bf[nt]);
    }

    // gate + write fp16 output
    #pragma unroll
    for (int mt = 0; mt < 2; mt++) {
        #pragma unroll
        for (int hh = 0; hh < 2; hh++) {
            int row = wmP + mt*16 + (lane>>2) + hh*8;
            float dinv = 1.f / drow[row];
            float linv = 1.f / lrow[row];
            size_t ob = ((size_t)b*SS + seg*SEG_ + qt*64 + row)*DD + h*DK_;
            #pragma unroll
            for (int nt = 0; nt < 4; nt++) {
                int col = wnP + nt*8 + (lane&3)*2;
                float g0 = 1.f / (1.f + __expf(-betas[h*DK_ + col]));
                float g1 = 1.f / (1.f + __expf(-betas[h*DK_ + col + 1]));
                float u0 = g0*(acc_m[mt][nt][hh*2]  *dinv) + (1.f-g0)*(acc_o[mt][nt][hh*2]  *linv);
                float u1 = g1*(acc_m[mt][nt][hh*2+1]*dinv) + (1.f-g1)*(acc_o[mt][nt][hh*2+1]*linv);
                *(__half2*)&Oah[ob + col] = __halves2half2(__float2half_rn(u0), __float2half_rn(u1));
            }
        }
    }
}

// ---------------- launch ----------------
extern "C" void kernel_launch(void* const* d_in, const int* in_sizes, int n_in,
                              void* d_out, int out_size)
{
    const float* x     = (const float*)d_in[0];
    const float* ln_g  = (const float*)d_in[1];
    const float* ln_b  = (const float*)d_in[2];
    const float* Wq    = (const float*)d_in[3];
    const float* Wk    = (const float*)d_in[4];
    const float* Wv    = (const float*)d_in[5];
    const float* Wo    = (const float*)d_in[6];
    const float* betas = (const float*)d_in[7];
    const float* w1    = (const float*)d_in[8];
    const float* b1    = (const float*)d_in[9];
    const float* w2    = (const float*)d_in[10];
    const float* b2    = (const float*)d_in[11];
    float* out = (float*)d_out;

    float *x1, *ff, *msp, *zsp, *zp;
    __half *qkvh, *mph, *ah, *bqkv, *bo, *bw1, *bw2;
    cudaGetSymbolAddress((void**)&qkvh, g_qkvh);
    cudaGetSymbolAddress((void**)&x1, g_x1);
    cudaGetSymbolAddress((void**)&ff, g_ff);
    cudaGetSymbolAddress((void**)&msp, g_msp);
    cudaGetSymbolAddress((void**)&mph, g_mph);
    cudaGetSymbolAddress((void**)&zsp, g_zsp);
    cudaGetSymbolAddress((void**)&zp, g_zp);
    cudaGetSymbolAddress((void**)&ah, g_ah);
    cudaGetSymbolAddress((void**)&bqkv, g_bqkv);
    cudaGetSymbolAddress((void**)&bo, g_bo);
    cudaGetSymbolAddress((void**)&bw1, g_bw1);
    cudaGetSymbolAddress((void**)&bw2, g_bw2);

    __half* ah2 = (__half*)ff;     // FFN1 hi-only output

    cudaFuncSetAttribute(attn_kernel, cudaFuncAttributeMaxDynamicSharedMemorySize, ATTN_SMEM);
    cudaFuncSetAttribute(hgemm_kernel, cudaFuncAttributeMaxDynamicSharedMemorySize, HG_SMEM);
    cudaFuncSetAttribute(segkv_kernel, cudaFuncAttributeMaxDynamicSharedMemorySize, SKV_SMEM);

    dim3 wblk(32, 8);

    // weight prep
    prep_w_kernel<<<dim3(1024/32, 1024/32), wblk>>>(Wq, bqkv,                      1024, 1024);
    prep_w_kernel<<<dim3(1024/32, 1024/32), wblk>>>(Wk, bqkv + (size_t)1024*1024,  1024, 1024);
    prep_w_kernel<<<dim3(1024/32, 1024/32), wblk>>>(Wv, bqkv + (size_t)2048*1024,  1024, 1024);
    prep_w_kernel<<<dim3(1024/32, 1024/32), wblk>>>(Wo, bo, 1024, 1024);
    prep_w_kernel<<<dim3(4096/32, 1024/32), wblk>>>(w1, bw1, 1024, 4096);
    prep_w_kernel<<<dim3(1024/32, 4096/32), wblk>>>(w2, bw2, 4096, 1024);

    // 1) LN1 -> fp16
    ln_kernel<<<MROWS, 256>>>(x, ln_g, ln_b, ah);
    // 2) fused QKV projection -> fp16 qkv
    hgemm_kernel<<<dim3(QS/128, MROWS/128), 256, HG_SMEM>>>(ah, bqkv, nullptr, nullptr,
                                                            nullptr, qkvh, MROWS, QS, QS, DD, 0, 2);
    // 3-5) infini-attention
    segkv_kernel<<<dim3(NSEG, BB*HH, NCH), 256, SKV_SMEM>>>(qkvh + 1024, qkvh + 2048, msp, zsp);
    prefix_kernel<<<(BB*HH*DK_*DK_)/256, 256>>>(msp, zsp, mph, zp);
    attn_kernel<<<dim3(8, NSEG, BB*HH), 256, ATTN_SMEM>>>(qkvh, qkvh + 1024, qkvh + 2048,
                                                          mph, zp, betas, ah);
    // 6) output projection + residual
    dim3 g1(DD/128, MROWS/128);
    hgemm_kernel<<<g1, 256, HG_SMEM>>>(ah, bo, nullptr, x, x1, nullptr,
                                       MROWS, DD, DD, DD, 0, 0);
    // 7) LN2 -> fp16
    ln_kernel<<<MROWS, 256>>>(x1, ln_g, ln_b, ah);
    // 8) FFN1 + bias + gelu -> fp16
    hgemm_kernel<<<dim3(DH_/128, MROWS/128), 256, HG_SMEM>>>(ah, bw1, b1, nullptr, nullptr,
                                                             ah2, MROWS, DH_, DH_, DD, 1, 2);
    // 9) FFN2 + bias + residual -> out
    hgemm_kernel<<<dim3(DD/128, MROWS/128), 256, HG_SMEM>>>(ah2, bw2, b2, x1, out,
                                                            nullptr, MROWS, DD, DD, DH_, 0, 0);
}